// round 2
// baseline (speedup 1.0000x reference)
#include <cuda_runtime.h>
#include <math.h>
#include <stdint.h>

#define Bb   8
#define LL   4096
#define DIMC 512
#define SS   32
#define KK   8
#define NT   (Bb*LL)      /* 32768 tokens */
#define NC   (DIMC*2)     /* 1024 floats per token (interleaved r,i) */
#define THRv 0.5f
#define EPSv 1e-8f

/* output layout: concat(out, new_keys, new_values, new_mask, salience) */
#define OFF_OUT ((size_t)0)
#define OFF_NK  ((size_t)NT*NC)                       /* 33554432 */
#define OFF_NV  (OFF_NK + (size_t)Bb*SS*NC)           /* +262144  */
#define OFF_NM  (OFF_NV + (size_t)Bb*SS*NC)           /* +262144  */
#define OFF_SAL (OFF_NM + (size_t)Bb*SS)              /* +256     */

/* scratch (device globals; no allocation allowed) */
__device__ float g_avg[NT];
__device__ float g_phase[NT];
__device__ float g_evec[Bb*SS*NC];
__device__ float g_emask[Bb*SS];
__device__ int   g_rs[Bb*SS];
__device__ int   g_re[Bb*SS];
__device__ float g_kmag[Bb*SS];
__device__ float g_Bmat[NC*NC];   /* expanded real B for query GEMM: 4MB */

__device__ __forceinline__ float wred(float v) {
    #pragma unroll
    for (int o = 16; o; o >>= 1) v += __shfl_xor_sync(0xffffffffu, v, o);
    return v;
}

/* ------------------------------------------------------------------ */
/* Build 1024x1024 real B-matrix from complex W_rq:
   row kk = input component, col nn = output component.
   B[2d][2e]=Wr[d][e], B[2d][2e+1]=Wi, B[2d+1][2e]=-Wi, B[2d+1][2e+1]=Wr */
__global__ void k_build_bmat(const float* __restrict__ Wr,
                             const float* __restrict__ Wi) {
    int idx = blockIdx.x * blockDim.x + threadIdx.x;  /* 0..512*512-1 */
    if (idx >= DIMC * DIMC) return;
    int d = idx / DIMC, e = idx % DIMC;
    float wr = Wr[idx], wi = Wi[idx];
    g_Bmat[(size_t)(2*d)   * NC + 2*e    ] =  wr;
    g_Bmat[(size_t)(2*d)   * NC + 2*e + 1] =  wi;
    g_Bmat[(size_t)(2*d+1) * NC + 2*e    ] = -wi;
    g_Bmat[(size_t)(2*d+1) * NC + 2*e + 1] =  wr;
}

/* ------------------------------------------------------------------ */
/* per-token: avg magnitude and salience-projection phase (warp/token) */
__global__ void k_stats(const float* __restrict__ z,
                        const float* __restrict__ Wsr,
                        const float* __restrict__ Wsi) {
    int gw = (blockIdx.x * blockDim.x + threadIdx.x) >> 5;
    int lane = threadIdx.x & 31;
    if (gw >= NT) return;
    const float4* z4 = (const float4*)(z + (size_t)gw * NC);
    float ms = 0.f, pr = 0.f, pi = 0.f;
    #pragma unroll
    for (int i = 0; i < 8; i++) {
        int p = lane + 32 * i;          /* float4 index -> complex dims 2p,2p+1 */
        float4 v = z4[p];
        int d = 2 * p;
        ms += sqrtf(v.x*v.x + v.y*v.y + EPSv) + sqrtf(v.z*v.z + v.w*v.w + EPSv);
        float wr0 = Wsr[d], wi0 = Wsi[d], wr1 = Wsr[d+1], wi1 = Wsi[d+1];
        pr += v.x*wr0 - v.y*wi0 + v.z*wr1 - v.w*wi1;
        pi += v.x*wi0 + v.y*wr0 + v.z*wi1 + v.w*wr1;
    }
    ms = wred(ms); pr = wred(pr); pi = wred(pi);
    if (lane == 0) {
        g_avg[gw]   = ms * (1.f / DIMC);
        g_phase[gw] = sqrtf(pr*pr + pi*pi + EPSv);
    }
}

/* salience = sigmoid(phase + (avg - 5tap_local_mean)*scale + bias) */
__global__ void k_salience(float* __restrict__ out,
                           const float* __restrict__ sb,
                           const float* __restrict__ ns) {
    int i = blockIdx.x * blockDim.x + threadIdx.x;
    if (i >= NT) return;
    int l = i & (LL - 1);
    float lm = 0.f;
    #pragma unroll
    for (int o = -2; o <= 2; o++) {
        int ll = l + o;
        if (ll >= 0 && ll < LL) lm += g_avg[i + o];
    }
    lm *= 0.2f;
    float x = g_phase[i] + (g_avg[i] - lm) * ns[0] + sb[0];
    out[OFF_SAL + i] = 1.f / (1.f + expf(-x));
}

/* ------------------------------------------------------------------ */
/* per-batch run detection: first SS maximal runs of salience>THR */
__global__ void k_runs(const float* __restrict__ out) {
    int b = blockIdx.x, tid = threadIdx.x;
    const float* s = out + OFF_SAL + (size_t)b * LL;
    __shared__ int scnt[256];
    int l0 = tid * 16;
    bool prev0 = (l0 > 0) && (s[l0 - 1] > THRv);
    bool pa = prev0;
    int cnt = 0;
    for (int j = 0; j < 16; j++) {
        bool ab = s[l0 + j] > THRv;
        cnt += (ab && !pa);
        pa = ab;
    }
    scnt[tid] = cnt;
    if (tid < SS) { g_rs[b*SS+tid] = 0; g_re[b*SS+tid] = 0; g_emask[b*SS+tid] = 0.f; }
    __syncthreads();
    if (tid == 0) {
        int a = 0;
        for (int t = 0; t < 256; t++) { int c = scnt[t]; scnt[t] = a; a += c; }
    }
    __syncthreads();
    int e = scnt[tid];
    pa = prev0;
    for (int j = 0; j < 16; j++) {
        int l = l0 + j;
        bool ab = s[l] > THRv;
        if (ab && !pa) {
            if (e < SS) { g_rs[b*SS + e] = l; g_emask[b*SS + e] = 1.f; }
            e++;
        }
        if (ab && (e - 1) < SS) {
            bool nx = (l + 1 < LL) && (s[l + 1] > THRv);
            if (!nx) g_re[b*SS + (e - 1)] = l + 1;
        }
        pa = ab;
    }
}

/* event vectors: weighted mean of z over each run (deterministic) */
__global__ void k_evec(const float* __restrict__ z,
                       const float* __restrict__ out) {
    int bs = blockIdx.x, b = bs / SS;
    int rs = g_rs[bs], re = g_re[bs];
    const float* sal = out + OFF_SAL + (size_t)b * LL;
    int t = threadIdx.x;
    float a0 = 0.f, a1 = 0.f, a2 = 0.f, a3 = 0.f, den = 0.f;
    for (int l = rs; l < re; l++) {
        float w = sal[l];
        den += w;
        const float* zt = z + ((size_t)b * LL + l) * NC;
        a0 += w * zt[t];       a1 += w * zt[t + 256];
        a2 += w * zt[t + 512]; a3 += w * zt[t + 768];
    }
    float inv = 1.f / fmaxf(den, EPSv);
    float* ev = g_evec + (size_t)bs * NC;
    ev[t] = a0 * inv; ev[t + 256] = a1 * inv;
    ev[t + 512] = a2 * inv; ev[t + 768] = a3 * inv;
}

/* ------------------------------------------------------------------ */
/* event keys/values projection + blend with slots + k_mag.
   grid (Bb, SS/2): 2 slots per block, 512 threads (thread = output dim e). */
__global__ void k_eventkv(const float* __restrict__ Wekr, const float* __restrict__ Weki,
                          const float* __restrict__ Wevr, const float* __restrict__ Wevi,
                          const float* __restrict__ sk,   const float* __restrict__ svv,
                          float* __restrict__ out) {
    int b = blockIdx.x, sg = blockIdx.y;
    int e = threadIdx.x;
    __shared__ float sv[2][NC];
    __shared__ float wpart[2][16];
    for (int i = threadIdx.x; i < 2 * NC; i += 512)
        ((float*)sv)[i] = g_evec[(size_t)(b * SS + sg * 2) * NC + i];
    __syncthreads();
    float KR[2] = {0.f, 0.f}, KI[2] = {0.f, 0.f};
    float VR[2] = {0.f, 0.f}, VI[2] = {0.f, 0.f};
    for (int d = 0; d < DIMC; d++) {
        float wkr = Wekr[d * DIMC + e], wki = Weki[d * DIMC + e];
        float wvr = Wevr[d * DIMC + e], wvi = Wevi[d * DIMC + e];
        #pragma unroll
        for (int s2 = 0; s2 < 2; s2++) {
            float zr = sv[s2][2 * d], zi = sv[s2][2 * d + 1];
            KR[s2] += zr * wkr - zi * wki;
            KI[s2] += zr * wki + zi * wkr;
            VR[s2] += zr * wvr - zi * wvi;
            VI[s2] += zr * wvi + zi * wvr;
        }
    }
    int lane = e & 31, wid = e >> 5;
    #pragma unroll
    for (int s2 = 0; s2 < 2; s2++) {
        int bs = b * SS + sg * 2 + s2;
        float m = g_emask[bs];
        size_t off = (size_t)bs * NC + 2 * e;
        float nkr = m * KR[s2] + (1.f - m) * sk[off];
        float nki = m * KI[s2] + (1.f - m) * sk[off + 1];
        float nvr = m * VR[s2] + (1.f - m) * svv[off];
        float nvi = m * VI[s2] + (1.f - m) * svv[off + 1];
        out[OFF_NK + off] = nkr; out[OFF_NK + off + 1] = nki;
        out[OFF_NV + off] = nvr; out[OFF_NV + off + 1] = nvi;
        float p = wred(nkr * nkr + nki * nki);
        if (lane == 0) wpart[s2][wid] = p;
    }
    __syncthreads();
    if (threadIdx.x < 2) {
        float sum = 0.f;
        for (int i = 0; i < 16; i++) sum += wpart[threadIdx.x][i];
        g_kmag[b * SS + sg * 2 + threadIdx.x] = sqrtf(sum + EPSv);
    }
}

__global__ void k_mask(const float* __restrict__ slot_mask, float* __restrict__ out) {
    int i = threadIdx.x;
    if (i < Bb * SS) out[OFF_NM + i] = fminf(slot_mask[i] + g_emask[i], 1.f);
}

/* ------------------------------------------------------------------ */
/* query GEMM: C[32768 x 1024] = z[32768 x 1024] * g_Bmat[1024 x 1024]
   128x128 tile, BK=8, 256 threads, 8x8 register tile. C = q region of out. */
__global__ void __launch_bounds__(256, 2)
k_qgemm(const float* __restrict__ A, float* __restrict__ C) {
    __shared__ float As[8][128];
    __shared__ float Bs[8][128];
    int tid  = threadIdx.x;
    int m0   = blockIdx.y * 128, n0 = blockIdx.x * 128;
    int ty   = tid >> 4, tx = tid & 15;
    int arow = tid >> 1, acol = (tid & 1) * 4;
    int bk   = tid >> 5, bn = (tid & 31) * 4;
    float acc[8][8];
    #pragma unroll
    for (int i = 0; i < 8; i++)
        #pragma unroll
        for (int j = 0; j < 8; j++) acc[i][j] = 0.f;

    for (int kk = 0; kk < NC; kk += 8) {
        float4 av = *(const float4*)(A + (size_t)(m0 + arow) * NC + kk + acol);
        float4 bv = *(const float4*)(g_Bmat + (size_t)(kk + bk) * NC + n0 + bn);
        __syncthreads();
        As[acol + 0][arow] = av.x; As[acol + 1][arow] = av.y;
        As[acol + 2][arow] = av.z; As[acol + 3][arow] = av.w;
        *(float4*)&Bs[bk][bn] = bv;
        __syncthreads();
        #pragma unroll
        for (int k = 0; k < 8; k++) {
            float a[8], bb[8];
            *(float4*)(a)      = *(const float4*)&As[k][ty * 8];
            *(float4*)(a + 4)  = *(const float4*)&As[k][ty * 8 + 4];
            *(float4*)(bb)     = *(const float4*)&Bs[k][tx * 8];
            *(float4*)(bb + 4) = *(const float4*)&Bs[k][tx * 8 + 4];
            #pragma unroll
            for (int i = 0; i < 8; i++)
                #pragma unroll
                for (int j = 0; j < 8; j++)
                    acc[i][j] = fmaf(a[i], bb[j], acc[i][j]);
        }
    }
    #pragma unroll
    for (int i = 0; i < 8; i++) {
        float* cr = C + (size_t)(m0 + ty * 8 + i) * NC + n0 + tx * 8;
        float4 o0 = make_float4(acc[i][0], acc[i][1], acc[i][2], acc[i][3]);
        float4 o1 = make_float4(acc[i][4], acc[i][5], acc[i][6], acc[i][7]);
        ((float4*)cr)[0] = o0;
        ((float4*)cr)[1] = o1;
    }
}

/* ------------------------------------------------------------------ */
/* attention: warp per token (8 tokens/block), keys then values staged in smem.
   q read from out region, out written back in place. */
__global__ void k_attn(float* __restrict__ out, const float* __restrict__ gain) {
    extern __shared__ float4 sKV[];            /* 32*256 float4 = 128KB dynamic */
    __shared__ float sKmag[SS];
    __shared__ float sMask[SS];
    int tid = threadIdx.x, warp = tid >> 5, lane = tid & 31;
    int tok0 = blockIdx.x * 8;
    int b = tok0 / LL;

    const float4* Ksrc = (const float4*)(out + OFF_NK + (size_t)b * SS * NC);
    for (int i = tid; i < SS * NC / 4; i += 256) sKV[i] = Ksrc[i];
    if (tid < SS) {
        sKmag[tid] = g_kmag[b * SS + tid];
        sMask[tid] = out[OFF_NM + b * SS + tid];
    }
    __syncthreads();

    int token = tok0 + warp;
    float4 q4[8];
    const float4* qrow = (const float4*)(out + (size_t)token * NC);
    #pragma unroll
    for (int i = 0; i < 8; i++) q4[i] = qrow[lane + 32 * i];

    float qs = 0.f;
    #pragma unroll
    for (int i = 0; i < 8; i++)
        qs += q4[i].x*q4[i].x + q4[i].y*q4[i].y + q4[i].z*q4[i].z + q4[i].w*q4[i].w;
    qs = wred(qs);
    float qmag = sqrtf(qs + EPSv);

    float myscore = -3e38f;
    for (int s = 0; s < SS; s++) {
        const float4* Kr = sKV + s * 256;
        float p = 0.f;
        #pragma unroll
        for (int i = 0; i < 8; i++) {
            float4 kv = Kr[lane + 32 * i];
            p += q4[i].x*kv.x + q4[i].y*kv.y + q4[i].z*kv.z + q4[i].w*kv.w;
        }
        p = wred(p);
        float sc = p / (qmag * sKmag[s] + EPSv);
        if (sMask[s] == 0.f) sc = -1e9f;
        if (lane == s) myscore = sc;
    }

    /* top-K with lowest-index tie break */
    float vcur = myscore;
    float topv[KK]; int topi[KK];
    #pragma unroll
    for (int j = 0; j < KK; j++) {
        float v = vcur; int idx = lane;
        #pragma unroll
        for (int o = 16; o; o >>= 1) {
            float v2 = __shfl_xor_sync(0xffffffffu, v, o);
            int   i2 = __shfl_xor_sync(0xffffffffu, idx, o);
            if (v2 > v || (v2 == v && i2 < idx)) { v = v2; idx = i2; }
        }
        topv[j] = v; topi[j] = idx;
        if (lane == idx) vcur = -INFINITY;
    }
    float w[KK], wsum = 0.f, mx = topv[0];
    #pragma unroll
    for (int j = 0; j < KK; j++) { w[j] = expf(topv[j] - mx); wsum += w[j]; }
    float winv = 1.f / wsum;

    __syncthreads();
    const float4* Vsrc = (const float4*)(out + OFF_NV + (size_t)b * SS * NC);
    for (int i = tid; i < SS * NC / 4; i += 256) sKV[i] = Vsrc[i];
    __syncthreads();

    float4 r[8];
    #pragma unroll
    for (int i = 0; i < 8; i++) r[i] = make_float4(0.f, 0.f, 0.f, 0.f);
    #pragma unroll
    for (int j = 0; j < KK; j++) {
        float a = w[j] * winv;
        const float4* Vr = sKV + topi[j] * 256;
        #pragma unroll
        for (int i = 0; i < 8; i++) {
            float4 vv = Vr[lane + 32 * i];
            r[i].x += a * vv.x; r[i].y += a * vv.y;
            r[i].z += a * vv.z; r[i].w += a * vv.w;
        }
    }
    float ssum = 0.f;
    #pragma unroll
    for (int i = 0; i < 8; i++)
        ssum += r[i].x*r[i].x + r[i].y*r[i].y + r[i].z*r[i].z + r[i].w*r[i].w;
    ssum = wred(ssum);
    float rinv = 1.f / sqrtf(ssum * (1.f / DIMC) + EPSv);

    const float2* g2 = (const float2*)gain;
    float4* orow = (float4*)(out + (size_t)token * NC);
    #pragma unroll
    for (int i = 0; i < 8; i++) {
        float2 g = g2[lane + 32 * i];
        float4 o;
        o.x = r[i].x * rinv * g.x; o.y = r[i].y * rinv * g.x;
        o.z = r[i].z * rinv * g.y; o.w = r[i].w * rinv * g.y;
        orow[lane + 32 * i] = o;
    }
}

/* ------------------------------------------------------------------ */
extern "C" void kernel_launch(void* const* d_in, const int* in_sizes, int n_in,
                              void* d_out, int out_size) {
    const float* z    = (const float*)d_in[0];
    const float* sk   = (const float*)d_in[1];
    const float* sv   = (const float*)d_in[2];
    const float* sm   = (const float*)d_in[3];
    const float* Wsr  = (const float*)d_in[4];
    const float* Wsi  = (const float*)d_in[5];
    const float* sb   = (const float*)d_in[6];
    const float* ns   = (const float*)d_in[7];
    const float* Wekr = (const float*)d_in[8];
    const float* Weki = (const float*)d_in[9];
    const float* Wevr = (const float*)d_in[10];
    const float* Wevi = (const float*)d_in[11];
    const float* Wrqr = (const float*)d_in[12];
    const float* Wrqi = (const float*)d_in[13];
    const float* gain = (const float*)d_in[14];
    float* out = (float*)d_out;

    static bool attr_done = false;
    if (!attr_done) {
        cudaFuncSetAttribute(k_attn, cudaFuncAttributeMaxDynamicSharedMemorySize, 131072);
        attr_done = true;
    }

    k_build_bmat<<<1024, 256>>>(Wrqr, Wrqi);
    k_stats<<<4096, 256>>>(z, Wsr, Wsi);
    k_salience<<<128, 256>>>(out, sb, ns);
    k_runs<<<Bb, 256>>>(out);
    k_evec<<<Bb * SS, 256>>>(z, out);
    k_eventkv<<<dim3(Bb, SS / 2), 512>>>(Wekr, Weki, Wevr, Wevi, sk, sv, out);
    k_mask<<<1, 256>>>(sm, out);
    k_qgemm<<<dim3(8, 256), 256>>>(z, out);
    k_attn<<<NT / 8, 256, 131072>>>(out, gain);
}

// round 5
// speedup vs baseline: 1.0212x; 1.0212x over previous
#include <cuda_runtime.h>
#include <cuda_bf16.h>
#include <math.h>
#include <stdint.h>

#define Bb   8
#define LL   4096
#define DIMC 512
#define SS   32
#define KK   8
#define NT   (Bb*LL)      /* 32768 tokens */
#define NC   (DIMC*2)     /* 1024 floats per token (interleaved r,i) */
#define THRv 0.5f
#define EPSv 1e-8f

/* output layout: concat(out, new_keys, new_values, new_mask, salience) */
#define OFF_OUT ((size_t)0)
#define OFF_NK  ((size_t)NT*NC)
#define OFF_NV  (OFF_NK + (size_t)Bb*SS*NC)
#define OFF_NM  (OFF_NV + (size_t)Bb*SS*NC)
#define OFF_SAL (OFF_NM + (size_t)Bb*SS)

/* scratch (device globals; no allocation allowed) */
__device__ float g_avg[NT];
__device__ float g_phase[NT];
__device__ float g_evec[Bb*SS*NC];
__device__ float g_emask[Bb*SS];
__device__ int   g_rs[Bb*SS];
__device__ int   g_re[Bb*SS];
__device__ float g_kmag[Bb*SS];
__device__ __nv_bfloat16 g_BhiT[NC*NC];          /* B^T hi, [n][k] */
__device__ __nv_bfloat16 g_BmdT[NC*NC];          /* B^T mid */
__device__ __nv_bfloat16 g_BloT[NC*NC];          /* B^T lo  */
__device__ __nv_bfloat16 g_Ahi[(size_t)NT*NC];   /* 64MB each */
__device__ __nv_bfloat16 g_Amd[(size_t)NT*NC];
__device__ __nv_bfloat16 g_Alo[(size_t)NT*NC];

__device__ __forceinline__ float wred(float v) {
    #pragma unroll
    for (int o = 16; o; o >>= 1) v += __shfl_xor_sync(0xffffffffu, v, o);
    return v;
}

__device__ __forceinline__ uint32_t smem_u32(const void* p) {
    uint32_t a;
    asm("{ .reg .u64 t; cvta.to.shared.u64 t, %1; cvt.u32.u64 %0, t; }"
        : "=r"(a) : "l"(p));
    return a;
}

/* split x into 3 bf16 components: x ~ h + m + l (residual ~2^-27) */
__device__ __forceinline__ void bsplit3(float x, __nv_bfloat16& h,
                                        __nv_bfloat16& m, __nv_bfloat16& l) {
    h = __float2bfloat16_rn(x);
    float r = x - __bfloat162float(h);
    m = __float2bfloat16_rn(r);
    l = __float2bfloat16_rn(r - __bfloat162float(m));
}

__device__ __forceinline__ void ldsm4(uint32_t* r, uint32_t addr) {
    asm volatile("ldmatrix.sync.aligned.m8n8.x4.shared.b16 {%0,%1,%2,%3}, [%4];"
        : "=r"(r[0]), "=r"(r[1]), "=r"(r[2]), "=r"(r[3]) : "r"(addr));
}

__device__ __forceinline__ void mma16816(float* d, const uint32_t* a,
                                         uint32_t b0, uint32_t b1) {
    asm volatile(
        "mma.sync.aligned.m16n8k16.row.col.f32.bf16.bf16.f32 "
        "{%0,%1,%2,%3}, {%4,%5,%6,%7}, {%8,%9}, {%0,%1,%2,%3};"
        : "+f"(d[0]), "+f"(d[1]), "+f"(d[2]), "+f"(d[3])
        : "r"(a[0]), "r"(a[1]), "r"(a[2]), "r"(a[3]), "r"(b0), "r"(b1));
}

/* ------------------------------------------------------------------ */
/* A pre-split: z fp32 -> g_Ahi/g_Amd/g_Alo bf16 (8 elems/thread) */
__global__ void k_preA(const float* __restrict__ z) {
    size_t i = ((size_t)blockIdx.x * 256 + threadIdx.x) * 8;
    float4 v0 = *(const float4*)(z + i);
    float4 v1 = *(const float4*)(z + i + 4);
    __nv_bfloat16 h[8], m[8], l[8];
    bsplit3(v0.x, h[0], m[0], l[0]); bsplit3(v0.y, h[1], m[1], l[1]);
    bsplit3(v0.z, h[2], m[2], l[2]); bsplit3(v0.w, h[3], m[3], l[3]);
    bsplit3(v1.x, h[4], m[4], l[4]); bsplit3(v1.y, h[5], m[5], l[5]);
    bsplit3(v1.z, h[6], m[6], l[6]); bsplit3(v1.w, h[7], m[7], l[7]);
    *(uint4*)(g_Ahi + i) = *(uint4*)h;
    *(uint4*)(g_Amd + i) = *(uint4*)m;
    *(uint4*)(g_Alo + i) = *(uint4*)l;
}

/* ------------------------------------------------------------------ */
/* Build transposed 3-way B (bf16): BT[2e][2d]=Wr, BT[2e][2d+1]=-Wi,
   BT[2e+1][2d]=Wi, BT[2e+1][2d+1]=Wr. Smem-tiled transpose. */
__global__ void k_build_bt(const float* __restrict__ Wr,
                           const float* __restrict__ Wi) {
    __shared__ float tr[32][33], ti[32][33];
    int tx = threadIdx.x & 31, ty = threadIdx.x >> 5;   /* 32 x 8 */
    int d0 = blockIdx.x * 32, e0 = blockIdx.y * 32;
    #pragma unroll
    for (int j = 0; j < 4; j++) {
        int d = d0 + ty + 8 * j;
        tr[ty + 8 * j][tx] = Wr[(size_t)d * DIMC + e0 + tx];
        ti[ty + 8 * j][tx] = Wi[(size_t)d * DIMC + e0 + tx];
    }
    __syncthreads();
    #pragma unroll
    for (int j = 0; j < 4; j++) {
        int e = e0 + ty + 8 * j;
        int d = d0 + tx;
        float wr = tr[tx][ty + 8 * j], wi = ti[tx][ty + 8 * j];
        __nv_bfloat16 h, m, l;
        size_t r0 = (size_t)(2 * e) * NC, r1 = (size_t)(2 * e + 1) * NC;
        bsplit3(wr, h, m, l);
        g_BhiT[r0 + 2*d]     = h; g_BmdT[r0 + 2*d]     = m; g_BloT[r0 + 2*d]     = l;
        g_BhiT[r1 + 2*d + 1] = h; g_BmdT[r1 + 2*d + 1] = m; g_BloT[r1 + 2*d + 1] = l;
        bsplit3(-wi, h, m, l);
        g_BhiT[r0 + 2*d + 1] = h; g_BmdT[r0 + 2*d + 1] = m; g_BloT[r0 + 2*d + 1] = l;
        bsplit3(wi, h, m, l);
        g_BhiT[r1 + 2*d]     = h; g_BmdT[r1 + 2*d]     = m; g_BloT[r1 + 2*d]     = l;
    }
}

/* ------------------------------------------------------------------ */
/* per-token: avg magnitude and salience-projection phase (warp/token) */
__global__ void k_stats(const float* __restrict__ z,
                        const float* __restrict__ Wsr,
                        const float* __restrict__ Wsi) {
    int gw = (blockIdx.x * blockDim.x + threadIdx.x) >> 5;
    int lane = threadIdx.x & 31;
    if (gw >= NT) return;
    const float4* z4 = (const float4*)(z + (size_t)gw * NC);
    float ms = 0.f, pr = 0.f, pi = 0.f;
    #pragma unroll
    for (int i = 0; i < 8; i++) {
        int p = lane + 32 * i;
        float4 v = z4[p];
        int d = 2 * p;
        ms += sqrtf(v.x*v.x + v.y*v.y + EPSv) + sqrtf(v.z*v.z + v.w*v.w + EPSv);
        float wr0 = Wsr[d], wi0 = Wsi[d], wr1 = Wsr[d+1], wi1 = Wsi[d+1];
        pr += v.x*wr0 - v.y*wi0 + v.z*wr1 - v.w*wi1;
        pi += v.x*wi0 + v.y*wr0 + v.z*wi1 + v.w*wr1;
    }
    ms = wred(ms); pr = wred(pr); pi = wred(pi);
    if (lane == 0) {
        g_avg[gw]   = ms * (1.f / DIMC);
        g_phase[gw] = sqrtf(pr*pr + pi*pi + EPSv);
    }
}

__global__ void k_salience(float* __restrict__ out,
                           const float* __restrict__ sb,
                           const float* __restrict__ ns) {
    int i = blockIdx.x * blockDim.x + threadIdx.x;
    if (i >= NT) return;
    int l = i & (LL - 1);
    float lm = 0.f;
    #pragma unroll
    for (int o = -2; o <= 2; o++) {
        int ll = l + o;
        if (ll >= 0 && ll < LL) lm += g_avg[i + o];
    }
    lm *= 0.2f;
    float x = g_phase[i] + (g_avg[i] - lm) * ns[0] + sb[0];
    out[OFF_SAL + i] = 1.f / (1.f + expf(-x));
}

/* per-batch run detection: first SS maximal runs of salience>THR */
__global__ void k_runs(const float* __restrict__ out) {
    int b = blockIdx.x, tid = threadIdx.x;
    const float* s = out + OFF_SAL + (size_t)b * LL;
    __shared__ int scnt[256];
    int l0 = tid * 16;
    bool prev0 = (l0 > 0) && (s[l0 - 1] > THRv);
    bool pa = prev0;
    int cnt = 0;
    for (int j = 0; j < 16; j++) {
        bool ab = s[l0 + j] > THRv;
        cnt += (ab && !pa);
        pa = ab;
    }
    scnt[tid] = cnt;
    if (tid < SS) { g_rs[b*SS+tid] = 0; g_re[b*SS+tid] = 0; g_emask[b*SS+tid] = 0.f; }
    __syncthreads();
    if (tid == 0) {
        int a = 0;
        for (int t = 0; t < 256; t++) { int c = scnt[t]; scnt[t] = a; a += c; }
    }
    __syncthreads();
    int e = scnt[tid];
    pa = prev0;
    for (int j = 0; j < 16; j++) {
        int l = l0 + j;
        bool ab = s[l] > THRv;
        if (ab && !pa) {
            if (e < SS) { g_rs[b*SS + e] = l; g_emask[b*SS + e] = 1.f; }
            e++;
        }
        if (ab && (e - 1) < SS) {
            bool nx = (l + 1 < LL) && (s[l + 1] > THRv);
            if (!nx) g_re[b*SS + (e - 1)] = l + 1;
        }
        pa = ab;
    }
}

/* event vectors: weighted mean of z over each run */
__global__ void k_evec(const float* __restrict__ z,
                       const float* __restrict__ out) {
    int bs = blockIdx.x, b = bs / SS;
    int rs = g_rs[bs], re = g_re[bs];
    const float* sal = out + OFF_SAL + (size_t)b * LL;
    int t = threadIdx.x;
    float a0 = 0.f, a1 = 0.f, a2 = 0.f, a3 = 0.f, den = 0.f;
    for (int l = rs; l < re; l++) {
        float w = sal[l];
        den += w;
        const float* zt = z + ((size_t)b * LL + l) * NC;
        a0 += w * zt[t];       a1 += w * zt[t + 256];
        a2 += w * zt[t + 512]; a3 += w * zt[t + 768];
    }
    float inv = 1.f / fmaxf(den, EPSv);
    float* ev = g_evec + (size_t)bs * NC;
    ev[t] = a0 * inv; ev[t + 256] = a1 * inv;
    ev[t + 512] = a2 * inv; ev[t + 768] = a3 * inv;
}

/* event keys/values projection + blend with slots + k_mag */
__global__ void k_eventkv(const float* __restrict__ Wekr, const float* __restrict__ Weki,
                          const float* __restrict__ Wevr, const float* __restrict__ Wevi,
                          const float* __restrict__ sk,   const float* __restrict__ svv,
                          float* __restrict__ out) {
    int b = blockIdx.x, sg = blockIdx.y;
    int e = threadIdx.x;
    __shared__ float sv[2][NC];
    __shared__ float wpart[2][16];
    for (int i = threadIdx.x; i < 2 * NC; i += 512)
        ((float*)sv)[i] = g_evec[(size_t)(b * SS + sg * 2) * NC + i];
    __syncthreads();
    float KR[2] = {0.f, 0.f}, KI[2] = {0.f, 0.f};
    float VR[2] = {0.f, 0.f}, VI[2] = {0.f, 0.f};
    for (int d = 0; d < DIMC; d++) {
        float wkr = Wekr[d * DIMC + e], wki = Weki[d * DIMC + e];
        float wvr = Wevr[d * DIMC + e], wvi = Wevi[d * DIMC + e];
        #pragma unroll
        for (int s2 = 0; s2 < 2; s2++) {
            float zr = sv[s2][2 * d], zi = sv[s2][2 * d + 1];
            KR[s2] += zr * wkr - zi * wki;
            KI[s2] += zr * wki + zi * wkr;
            VR[s2] += zr * wvr - zi * wvi;
            VI[s2] += zr * wvi + zi * wvr;
        }
    }
    int lane = e & 31, wid = e >> 5;
    #pragma unroll
    for (int s2 = 0; s2 < 2; s2++) {
        int bs = b * SS + sg * 2 + s2;
        float m = g_emask[bs];
        size_t off = (size_t)bs * NC + 2 * e;
        float nkr = m * KR[s2] + (1.f - m) * sk[off];
        float nki = m * KI[s2] + (1.f - m) * sk[off + 1];
        float nvr = m * VR[s2] + (1.f - m) * svv[off];
        float nvi = m * VI[s2] + (1.f - m) * svv[off + 1];
        out[OFF_NK + off] = nkr; out[OFF_NK + off + 1] = nki;
        out[OFF_NV + off] = nvr; out[OFF_NV + off + 1] = nvi;
        float p = wred(nkr * nkr + nki * nki);
        if (lane == 0) wpart[s2][wid] = p;
    }
    __syncthreads();
    if (threadIdx.x < 2) {
        float sum = 0.f;
        for (int i = 0; i < 16; i++) sum += wpart[threadIdx.x][i];
        g_kmag[b * SS + sg * 2 + threadIdx.x] = sqrtf(sum + EPSv);
    }
}

__global__ void k_mask(const float* __restrict__ slot_mask, float* __restrict__ out) {
    int i = threadIdx.x;
    if (i < Bb * SS) out[OFF_NM + i] = fminf(slot_mask[i] + g_emask[i], 1.f);
}

/* ------------------------------------------------------------------ */
/* 6-term 3xBF16 mma.sync query GEMM:
   C = z*B with A,B each split h+m+l; accumulate hh,hm,mh,hl,mm,lh.
   BM=128, BN=128, BK=32, 256 thr (8 warps, warp tile 32x64),
   smem 80B row pitch, double-buffered, 6 component tiles per stage. */
#define BM 128
#define BN 128
#define BKq 32
#define PITCH 80
#define COMP_SZ (BM * PITCH)          /* 10240 */
#define STAGE_SZ (6 * COMP_SZ)        /* 61440: Ah,Am,Al,Bh,Bm,Bl */
#define QSMEM (2 * STAGE_SZ)          /* 122880 */
#define NIT (NC / BKq)                /* 32 */

__global__ void __launch_bounds__(256, 1)
k_qgemm_mma(float* __restrict__ C) {
    extern __shared__ unsigned char smq[];
    int t = threadIdx.x, lane = t & 31, wid = t >> 5;
    int m0 = blockIdx.y * BM, n0 = blockIdx.x * BN;
    int warpM = (wid & 3) * 32, warpN = (wid >> 2) * 64;
    int row2 = t >> 1, half = t & 1;

    const uint4* sAh = (const uint4*)(g_Ahi  + (size_t)(m0 + row2) * NC);
    const uint4* sAm = (const uint4*)(g_Amd  + (size_t)(m0 + row2) * NC);
    const uint4* sAl = (const uint4*)(g_Alo  + (size_t)(m0 + row2) * NC);
    const uint4* sBh = (const uint4*)(g_BhiT + (size_t)(n0 + row2) * NC);
    const uint4* sBm = (const uint4*)(g_BmdT + (size_t)(n0 + row2) * NC);
    const uint4* sBl = (const uint4*)(g_BloT + (size_t)(n0 + row2) * NC);

    int srow = row2 * PITCH + half * 32;

    uint32_t sb0 = smem_u32(smq);
    uint32_t aoff = (uint32_t)((warpM + (lane & 15)) * PITCH + ((lane >> 4) << 4));
    uint32_t boff = (uint32_t)((warpN + (lane & 7) + ((lane >> 4) & 1) * 8) * PITCH
                               + (((lane >> 3) & 1) << 4));

    float acc[2][8][4];
    #pragma unroll
    for (int i = 0; i < 2; i++)
        #pragma unroll
        for (int j = 0; j < 8; j++)
            #pragma unroll
            for (int k = 0; k < 4; k++) acc[i][j][k] = 0.f;

    /* stage 0 preload */
    {
        int idx = half * 2;
        #pragma unroll
        for (int u = 0; u < 2; u++) {
            *(uint4*)(smq + 0*COMP_SZ + srow + 16*u) = sAh[idx + u];
            *(uint4*)(smq + 1*COMP_SZ + srow + 16*u) = sAm[idx + u];
            *(uint4*)(smq + 2*COMP_SZ + srow + 16*u) = sAl[idx + u];
            *(uint4*)(smq + 3*COMP_SZ + srow + 16*u) = sBh[idx + u];
            *(uint4*)(smq + 4*COMP_SZ + srow + 16*u) = sBm[idx + u];
            *(uint4*)(smq + 5*COMP_SZ + srow + 16*u) = sBl[idx + u];
        }
    }
    __syncthreads();

    for (int it = 0; it < NIT; it++) {
        /* start filling next stage (independent buffer; sync at loop end) */
        if (it < NIT - 1) {
            int idx = (it + 1) * 4 + half * 2;
            unsigned char* sn = smq + ((it + 1) & 1) * STAGE_SZ;
            #pragma unroll
            for (int u = 0; u < 2; u++) {
                *(uint4*)(sn + 0*COMP_SZ + srow + 16*u) = sAh[idx + u];
                *(uint4*)(sn + 1*COMP_SZ + srow + 16*u) = sAm[idx + u];
                *(uint4*)(sn + 2*COMP_SZ + srow + 16*u) = sAl[idx + u];
                *(uint4*)(sn + 3*COMP_SZ + srow + 16*u) = sBh[idx + u];
                *(uint4*)(sn + 4*COMP_SZ + srow + 16*u) = sBm[idx + u];
                *(uint4*)(sn + 5*COMP_SZ + srow + 16*u) = sBl[idx + u];
            }
        }

        uint32_t st = sb0 + (uint32_t)((it & 1) * STAGE_SZ);
        uint32_t aAh = st + aoff;
        uint32_t aAm = st + 1*COMP_SZ + aoff;
        uint32_t aAl = st + 2*COMP_SZ + aoff;
        uint32_t aBh = st + 3*COMP_SZ + boff;
        uint32_t aBm = st + 4*COMP_SZ + boff;
        uint32_t aBl = st + 5*COMP_SZ + boff;

        #pragma unroll
        for (int ko = 0; ko < 2; ko++) {
            uint32_t ah[2][4], am[2][4], al[2][4];
            uint32_t bh[4][4], bm[4][4], bl[4][4];
            #pragma unroll
            for (int mg = 0; mg < 2; mg++) {
                ldsm4(ah[mg], aAh + mg * (16 * PITCH) + ko * 32);
                ldsm4(am[mg], aAm + mg * (16 * PITCH) + ko * 32);
                ldsm4(al[mg], aAl + mg * (16 * PITCH) + ko * 32);
            }
            #pragma unroll
            for (int ng = 0; ng < 4; ng++) {
                ldsm4(bh[ng], aBh + ng * (16 * PITCH) + ko * 32);
                ldsm4(bm[ng], aBm + ng * (16 * PITCH) + ko * 32);
                ldsm4(bl[ng], aBl + ng * (16 * PITCH) + ko * 32);
            }
            #pragma unroll
            for (int mg = 0; mg < 2; mg++)
                #pragma unroll
                for (int ng = 0; ng < 4; ng++)
                    #pragma unroll
                    for (int h = 0; h < 2; h++) {
                        float* d = acc[mg][ng * 2 + h];
                        /* magnitude order: smallest groups still fp32-safe */
                        mma16816(d, al[mg], bh[ng][h*2], bh[ng][h*2+1]); /* lh 2^-18 */
                        mma16816(d, am[mg], bm[ng][h*2], bm[ng][h*2+1]); /* mm 2^-18 */
                        mma16816(d, ah[mg], bl[ng][h*2], bl[ng][h*2+1]); /* hl 2^-18 */
                        mma16816(d, am[mg], bh[ng][h*2], bh[ng][h*2+1]); /* mh 2^-9  */
                        mma16816(d, ah[mg], bm[ng][h*2], bm[ng][h*2+1]); /* hm 2^-9  */
                        mma16816(d, ah[mg], bh[ng][h*2], bh[ng][h*2+1]); /* hh 1     */
                    }
        }
        __syncthreads();
    }

    /* epilogue: direct float2 stores */
    #pragma unroll
    for (int mg = 0; mg < 2; mg++)
        #pragma unroll
        for (int ng = 0; ng < 4; ng++)
            #pragma unroll
            for (int h = 0; h < 2; h++) {
                float* d = acc[mg][ng * 2 + h];
                int r = m0 + warpM + mg * 16 + (lane >> 2);
                int c = n0 + warpN + (ng * 2 + h) * 8 + (lane & 3) * 2;
                *(float2*)&C[(size_t)r * NC + c]       = make_float2(d[0], d[1]);
                *(float2*)&C[(size_t)(r + 8) * NC + c] = make_float2(d[2], d[3]);
            }
}

/* ------------------------------------------------------------------ */
/* attention: warp per token, 16 tokens/block (512 thr), K then V in smem */
__global__ void k_attn(float* __restrict__ out, const float* __restrict__ gain) {
    extern __shared__ float4 sKV[];            /* 32*256 float4 = 128KB */
    __shared__ float sKmag[SS];
    __shared__ float sMask[SS];
    int tid = threadIdx.x, warp = tid >> 5, lane = tid & 31;
    int tok0 = blockIdx.x * 16;
    int b = tok0 / LL;

    const float4* Ksrc = (const float4*)(out + OFF_NK + (size_t)b * SS * NC);
    for (int i = tid; i < SS * NC / 4; i += 512) sKV[i] = Ksrc[i];
    if (tid < SS) {
        sKmag[tid] = g_kmag[b * SS + tid];
        sMask[tid] = out[OFF_NM + b * SS + tid];
    }
    __syncthreads();

    int token = tok0 + warp;
    float4 q4[8];
    const float4* qrow = (const float4*)(out + (size_t)token * NC);
    #pragma unroll
    for (int i = 0; i < 8; i++) q4[i] = qrow[lane + 32 * i];

    float qs = 0.f;
    #pragma unroll
    for (int i = 0; i < 8; i++)
        qs += q4[i].x*q4[i].x + q4[i].y*q4[i].y + q4[i].z*q4[i].z + q4[i].w*q4[i].w;
    qs = wred(qs);
    float qmag = sqrtf(qs + EPSv);

    float myscore = -3e38f;
    for (int s = 0; s < SS; s++) {
        const float4* Kr = sKV + s * 256;
        float p = 0.f;
        #pragma unroll
        for (int i = 0; i < 8; i++) {
            float4 kv = Kr[lane + 32 * i];
            p += q4[i].x*kv.x + q4[i].y*kv.y + q4[i].z*kv.z + q4[i].w*kv.w;
        }
        p = wred(p);
        float sc = p / (qmag * sKmag[s] + EPSv);
        if (sMask[s] == 0.f) sc = -1e9f;
        if (lane == s) myscore = sc;
    }

    /* top-K with lowest-index tie break */
    float vcur = myscore;
    float topv[KK]; int topi[KK];
    #pragma unroll
    for (int j = 0; j < KK; j++) {
        float v = vcur; int idx = lane;
        #pragma unroll
        for (int o = 16; o; o >>= 1) {
            float v2 = __shfl_xor_sync(0xffffffffu, v, o);
            int   i2 = __shfl_xor_sync(0xffffffffu, idx, o);
            if (v2 > v || (v2 == v && i2 < idx)) { v = v2; idx = i2; }
        }
        topv[j] = v; topi[j] = idx;
        if (lane == idx) vcur = -INFINITY;
    }
    float w[KK], wsum = 0.f, mx = topv[0];
    #pragma unroll
    for (int j = 0; j < KK; j++) { w[j] = expf(topv[j] - mx); wsum += w[j]; }
    float winv = 1.f / wsum;

    __syncthreads();
    const float4* Vsrc = (const float4*)(out + OFF_NV + (size_t)b * SS * NC);
    for (int i = tid; i < SS * NC / 4; i += 512) sKV[i] = Vsrc[i];
    __syncthreads();

    float4 r[8];
    #pragma unroll
    for (int i = 0; i < 8; i++) r[i] = make_float4(0.f, 0.f, 0.f, 0.f);
    #pragma unroll
    for (int j = 0; j < KK; j++) {
        float a = w[j] * winv;
        const float4* Vr = sKV + topi[j] * 256;
        #pragma unroll
        for (int i = 0; i < 8; i++) {
            float4 vv = Vr[lane + 32 * i];
            r[i].x += a * vv.x; r[i].y += a * vv.y;
            r[i].z += a * vv.z; r[i].w += a * vv.w;
        }
    }
    float ssum = 0.f;
    #pragma unroll
    for (int i = 0; i < 8; i++)
        ssum += r[i].x*r[i].x + r[i].y*r[i].y + r[i].z*r[i].z + r[i].w*r[i].w;
    ssum = wred(ssum);
    float rinv = 1.f / sqrtf(ssum * (1.f / DIMC) + EPSv);

    const float2* g2 = (const float2*)gain;
    float4* orow = (float4*)(out + (size_t)token * NC);
    #pragma unroll
    for (int i = 0; i < 8; i++) {
        float2 g = g2[lane + 32 * i];
        float4 o;
        o.x = r[i].x * rinv * g.x; o.y = r[i].y * rinv * g.x;
        o.z = r[i].z * rinv * g.y; o.w = r[i].w * rinv * g.y;
        orow[lane + 32 * i] = o;
    }
}

/* ------------------------------------------------------------------ */
extern "C" void kernel_launch(void* const* d_in, const int* in_sizes, int n_in,
                              void* d_out, int out_size) {
    const float* z    = (const float*)d_in[0];
    const float* sk   = (const float*)d_in[1];
    const float* sv   = (const float*)d_in[2];
    const float* sm   = (const float*)d_in[3];
    const float* Wsr  = (const float*)d_in[4];
    const float* Wsi  = (const float*)d_in[5];
    const float* sb   = (const float*)d_in[6];
    const float* ns   = (const float*)d_in[7];
    const float* Wekr = (const float*)d_in[8];
    const float* Weki = (const float*)d_in[9];
    const float* Wevr = (const float*)d_in[10];
    const float* Wevi = (const float*)d_in[11];
    const float* Wrqr = (const float*)d_in[12];
    const float* Wrqi = (const float*)d_in[13];
    const float* gain = (const float*)d_in[14];
    float* out = (float*)d_out;

    static bool attr_done = false;
    if (!attr_done) {
        cudaFuncSetAttribute(k_attn, cudaFuncAttributeMaxDynamicSharedMemorySize, 131072);
        cudaFuncSetAttribute(k_qgemm_mma, cudaFuncAttributeMaxDynamicSharedMemorySize, QSMEM);
        attr_done = true;
    }

    k_preA<<<NT * NC / (256 * 8), 256>>>(z);
    k_build_bt<<<dim3(16, 16), 256>>>(Wrqr, Wrqi);
    k_stats<<<4096, 256>>>(z, Wsr, Wsi);
    k_salience<<<128, 256>>>(out, sb, ns);
    k_runs<<<Bb, 256>>>(out);
    k_evec<<<Bb * SS, 256>>>(z, out);
    k_eventkv<<<dim3(Bb, SS / 2), 512>>>(Wekr, Weki, Wevr, Wevi, sk, sv, out);
    k_mask<<<1, 256>>>(sm, out);
    k_qgemm_mma<<<dim3(NC / BN, NT / BM), 256, QSMEM>>>(out);
    k_attn<<<NT / 16, 512, 131072>>>(out, gain);
}

// round 6
// speedup vs baseline: 1.5979x; 1.5647x over previous
#include <cuda_runtime.h>
#include <cuda_fp16.h>
#include <math.h>
#include <stdint.h>

#define Bb   8
#define LL   4096
#define DIMC 512
#define SS   32
#define KK   8
#define NT   (Bb*LL)      /* 32768 tokens */
#define NC   (DIMC*2)     /* 1024 floats per token (interleaved r,i) */
#define THRv 0.5f
#define EPSv 1e-8f

/* output layout: concat(out, new_keys, new_values, new_mask, salience) */
#define OFF_OUT ((size_t)0)
#define OFF_NK  ((size_t)NT*NC)
#define OFF_NV  (OFF_NK + (size_t)Bb*SS*NC)
#define OFF_NM  (OFF_NV + (size_t)Bb*SS*NC)
#define OFF_SAL (OFF_NM + (size_t)Bb*SS)

/* scratch (device globals; no allocation allowed) */
__device__ float g_avg[NT];
__device__ float g_phase[NT];
__device__ float g_evec[Bb*SS*NC];
__device__ float g_emask[Bb*SS];
__device__ int   g_rs[Bb*SS];
__device__ int   g_re[Bb*SS];
__device__ float g_kmag[Bb*SS];
__device__ __half g_BhiT[NC*NC];          /* B^T hi (fp16), [n][k] */
__device__ __half g_BloT[NC*NC];          /* B^T lo residual      */
__device__ __half g_Ahi[(size_t)NT*NC];   /* 64MB */
__device__ __half g_Alo[(size_t)NT*NC];   /* 64MB */

__device__ __forceinline__ float wred(float v) {
    #pragma unroll
    for (int o = 16; o; o >>= 1) v += __shfl_xor_sync(0xffffffffu, v, o);
    return v;
}

__device__ __forceinline__ uint32_t smem_u32(const void* p) {
    uint32_t a;
    asm("{ .reg .u64 t; cvta.to.shared.u64 t, %1; cvt.u32.u64 %0, t; }"
        : "=r"(a) : "l"(p));
    return a;
}

/* split x into fp16 hi + fp16 lo residual (combined residual ~2^-23) */
__device__ __forceinline__ void hsplit(float x, __half& h, __half& l) {
    h = __float2half_rn(x);
    l = __float2half_rn(x - __half2float(h));
}

__device__ __forceinline__ void ldsm4(uint32_t* r, uint32_t addr) {
    asm volatile("ldmatrix.sync.aligned.m8n8.x4.shared.b16 {%0,%1,%2,%3}, [%4];"
        : "=r"(r[0]), "=r"(r[1]), "=r"(r[2]), "=r"(r[3]) : "r"(addr));
}

__device__ __forceinline__ void mma16816(float* d, const uint32_t* a,
                                         uint32_t b0, uint32_t b1) {
    asm volatile(
        "mma.sync.aligned.m16n8k16.row.col.f32.f16.f16.f32 "
        "{%0,%1,%2,%3}, {%4,%5,%6,%7}, {%8,%9}, {%0,%1,%2,%3};"
        : "+f"(d[0]), "+f"(d[1]), "+f"(d[2]), "+f"(d[3])
        : "r"(a[0]), "r"(a[1]), "r"(a[2]), "r"(a[3]), "r"(b0), "r"(b1));
}

/* ------------------------------------------------------------------ */
/* A pre-split: z fp32 -> g_Ahi/g_Alo fp16 (8 elems/thread) */
__global__ void k_preA(const float* __restrict__ z) {
    size_t i = ((size_t)blockIdx.x * 256 + threadIdx.x) * 8;
    float4 v0 = *(const float4*)(z + i);
    float4 v1 = *(const float4*)(z + i + 4);
    __half h[8], l[8];
    hsplit(v0.x, h[0], l[0]); hsplit(v0.y, h[1], l[1]);
    hsplit(v0.z, h[2], l[2]); hsplit(v0.w, h[3], l[3]);
    hsplit(v1.x, h[4], l[4]); hsplit(v1.y, h[5], l[5]);
    hsplit(v1.z, h[6], l[6]); hsplit(v1.w, h[7], l[7]);
    *(uint4*)(g_Ahi + i) = *(uint4*)h;
    *(uint4*)(g_Alo + i) = *(uint4*)l;
}

/* ------------------------------------------------------------------ */
/* Build transposed hi/lo B (fp16): BT[2e][2d]=Wr, BT[2e][2d+1]=-Wi,
   BT[2e+1][2d]=Wi, BT[2e+1][2d+1]=Wr. Smem-tiled transpose. */
__global__ void k_build_bt(const float* __restrict__ Wr,
                           const float* __restrict__ Wi) {
    __shared__ float tr[32][33], ti[32][33];
    int tx = threadIdx.x & 31, ty = threadIdx.x >> 5;   /* 32 x 8 */
    int d0 = blockIdx.x * 32, e0 = blockIdx.y * 32;
    #pragma unroll
    for (int j = 0; j < 4; j++) {
        int d = d0 + ty + 8 * j;
        tr[ty + 8 * j][tx] = Wr[(size_t)d * DIMC + e0 + tx];
        ti[ty + 8 * j][tx] = Wi[(size_t)d * DIMC + e0 + tx];
    }
    __syncthreads();
    #pragma unroll
    for (int j = 0; j < 4; j++) {
        int e = e0 + ty + 8 * j;
        int d = d0 + tx;
        float wr = tr[tx][ty + 8 * j], wi = ti[tx][ty + 8 * j];
        __half h, l;
        size_t r0 = (size_t)(2 * e) * NC, r1 = (size_t)(2 * e + 1) * NC;
        hsplit(wr, h, l);
        g_BhiT[r0 + 2*d]     = h; g_BloT[r0 + 2*d]     = l;
        g_BhiT[r1 + 2*d + 1] = h; g_BloT[r1 + 2*d + 1] = l;
        hsplit(-wi, h, l);
        g_BhiT[r0 + 2*d + 1] = h; g_BloT[r0 + 2*d + 1] = l;
        hsplit(wi, h, l);
        g_BhiT[r1 + 2*d]     = h; g_BloT[r1 + 2*d]     = l;
    }
}

/* ------------------------------------------------------------------ */
/* per-token: avg magnitude and salience-projection phase (warp/token) */
__global__ void k_stats(const float* __restrict__ z,
                        const float* __restrict__ Wsr,
                        const float* __restrict__ Wsi) {
    int gw = (blockIdx.x * blockDim.x + threadIdx.x) >> 5;
    int lane = threadIdx.x & 31;
    if (gw >= NT) return;
    const float4* z4 = (const float4*)(z + (size_t)gw * NC);
    float ms = 0.f, pr = 0.f, pi = 0.f;
    #pragma unroll
    for (int i = 0; i < 8; i++) {
        int p = lane + 32 * i;
        float4 v = z4[p];
        int d = 2 * p;
        ms += sqrtf(v.x*v.x + v.y*v.y + EPSv) + sqrtf(v.z*v.z + v.w*v.w + EPSv);
        float wr0 = Wsr[d], wi0 = Wsi[d], wr1 = Wsr[d+1], wi1 = Wsi[d+1];
        pr += v.x*wr0 - v.y*wi0 + v.z*wr1 - v.w*wi1;
        pi += v.x*wi0 + v.y*wr0 + v.z*wi1 + v.w*wr1;
    }
    ms = wred(ms); pr = wred(pr); pi = wred(pi);
    if (lane == 0) {
        g_avg[gw]   = ms * (1.f / DIMC);
        g_phase[gw] = sqrtf(pr*pr + pi*pi + EPSv);
    }
}

__global__ void k_salience(float* __restrict__ out,
                           const float* __restrict__ sb,
                           const float* __restrict__ ns) {
    int i = blockIdx.x * blockDim.x + threadIdx.x;
    if (i >= NT) return;
    int l = i & (LL - 1);
    float lm = 0.f;
    #pragma unroll
    for (int o = -2; o <= 2; o++) {
        int ll = l + o;
        if (ll >= 0 && ll < LL) lm += g_avg[i + o];
    }
    lm *= 0.2f;
    float x = g_phase[i] + (g_avg[i] - lm) * ns[0] + sb[0];
    out[OFF_SAL + i] = 1.f / (1.f + expf(-x));
}

/* per-batch run detection: first SS maximal runs of salience>THR */
__global__ void k_runs(const float* __restrict__ out) {
    int b = blockIdx.x, tid = threadIdx.x;
    const float* s = out + OFF_SAL + (size_t)b * LL;
    __shared__ int scnt[256];
    int l0 = tid * 16;
    bool prev0 = (l0 > 0) && (s[l0 - 1] > THRv);
    bool pa = prev0;
    int cnt = 0;
    for (int j = 0; j < 16; j++) {
        bool ab = s[l0 + j] > THRv;
        cnt += (ab && !pa);
        pa = ab;
    }
    scnt[tid] = cnt;
    if (tid < SS) { g_rs[b*SS+tid] = 0; g_re[b*SS+tid] = 0; g_emask[b*SS+tid] = 0.f; }
    __syncthreads();
    if (tid == 0) {
        int a = 0;
        for (int t = 0; t < 256; t++) { int c = scnt[t]; scnt[t] = a; a += c; }
    }
    __syncthreads();
    int e = scnt[tid];
    pa = prev0;
    for (int j = 0; j < 16; j++) {
        int l = l0 + j;
        bool ab = s[l] > THRv;
        if (ab && !pa) {
            if (e < SS) { g_rs[b*SS + e] = l; g_emask[b*SS + e] = 1.f; }
            e++;
        }
        if (ab && (e - 1) < SS) {
            bool nx = (l + 1 < LL) && (s[l + 1] > THRv);
            if (!nx) g_re[b*SS + (e - 1)] = l + 1;
        }
        pa = ab;
    }
}

/* event vectors: weighted mean of z over each run */
__global__ void k_evec(const float* __restrict__ z,
                       const float* __restrict__ out) {
    int bs = blockIdx.x, b = bs / SS;
    int rs = g_rs[bs], re = g_re[bs];
    const float* sal = out + OFF_SAL + (size_t)b * LL;
    int t = threadIdx.x;
    float a0 = 0.f, a1 = 0.f, a2 = 0.f, a3 = 0.f, den = 0.f;
    for (int l = rs; l < re; l++) {
        float w = sal[l];
        den += w;
        const float* zt = z + ((size_t)b * LL + l) * NC;
        a0 += w * zt[t];       a1 += w * zt[t + 256];
        a2 += w * zt[t + 512]; a3 += w * zt[t + 768];
    }
    float inv = 1.f / fmaxf(den, EPSv);
    float* ev = g_evec + (size_t)bs * NC;
    ev[t] = a0 * inv; ev[t + 256] = a1 * inv;
    ev[t + 512] = a2 * inv; ev[t + 768] = a3 * inv;
}

/* event keys/values projection + blend with slots + k_mag */
__global__ void k_eventkv(const float* __restrict__ Wekr, const float* __restrict__ Weki,
                          const float* __restrict__ Wevr, const float* __restrict__ Wevi,
                          const float* __restrict__ sk,   const float* __restrict__ svv,
                          float* __restrict__ out) {
    int b = blockIdx.x, sg = blockIdx.y;
    int e = threadIdx.x;
    __shared__ float sv[2][NC];
    __shared__ float wpart[2][16];
    for (int i = threadIdx.x; i < 2 * NC; i += 512)
        ((float*)sv)[i] = g_evec[(size_t)(b * SS + sg * 2) * NC + i];
    __syncthreads();
    float KR[2] = {0.f, 0.f}, KI[2] = {0.f, 0.f};
    float VR[2] = {0.f, 0.f}, VI[2] = {0.f, 0.f};
    for (int d = 0; d < DIMC; d++) {
        float wkr = Wekr[d * DIMC + e], wki = Weki[d * DIMC + e];
        float wvr = Wevr[d * DIMC + e], wvi = Wevi[d * DIMC + e];
        #pragma unroll
        for (int s2 = 0; s2 < 2; s2++) {
            float zr = sv[s2][2 * d], zi = sv[s2][2 * d + 1];
            KR[s2] += zr * wkr - zi * wki;
            KI[s2] += zr * wki + zi * wkr;
            VR[s2] += zr * wvr - zi * wvi;
            VI[s2] += zr * wvi + zi * wvr;
        }
    }
    int lane = e & 31, wid = e >> 5;
    #pragma unroll
    for (int s2 = 0; s2 < 2; s2++) {
        int bs = b * SS + sg * 2 + s2;
        float m = g_emask[bs];
        size_t off = (size_t)bs * NC + 2 * e;
        float nkr = m * KR[s2] + (1.f - m) * sk[off];
        float nki = m * KI[s2] + (1.f - m) * sk[off + 1];
        float nvr = m * VR[s2] + (1.f - m) * svv[off];
        float nvi = m * VI[s2] + (1.f - m) * svv[off + 1];
        out[OFF_NK + off] = nkr; out[OFF_NK + off + 1] = nki;
        out[OFF_NV + off] = nvr; out[OFF_NV + off + 1] = nvi;
        float p = wred(nkr * nkr + nki * nki);
        if (lane == 0) wpart[s2][wid] = p;
    }
    __syncthreads();
    if (threadIdx.x < 2) {
        float sum = 0.f;
        for (int i = 0; i < 16; i++) sum += wpart[threadIdx.x][i];
        g_kmag[b * SS + sg * 2 + threadIdx.x] = sqrtf(sum + EPSv);
    }
}

__global__ void k_mask(const float* __restrict__ slot_mask, float* __restrict__ out) {
    int i = threadIdx.x;
    if (i < Bb * SS) out[OFF_NM + i] = fminf(slot_mask[i] + g_emask[i], 1.f);
}

/* ------------------------------------------------------------------ */
/* 3-term FP16 mma.sync query GEMM:
   C = z*B with A,B each split h+l (fp16, residual ~2^-23);
   accumulate hh, hl, lh (drop ll ~ 2^-24).
   BM=128, BN=128, BK=32, 256 thr (8 warps, warp tile 32x64),
   smem 80B row pitch, double-buffered, 4 component tiles per stage,
   2 CTAs/SM. */
#define BM 128
#define BN 128
#define BKq 32
#define PITCH 80
#define COMP_SZ (BM * PITCH)          /* 10240 */
#define STAGE_SZ (4 * COMP_SZ)        /* 40960: Ah,Al,Bh,Bl */
#define QSMEM (2 * STAGE_SZ)          /* 81920 */
#define NIT (NC / BKq)                /* 32 */

__global__ void __launch_bounds__(256, 2)
k_qgemm_mma(float* __restrict__ C) {
    extern __shared__ unsigned char smq[];
    int t = threadIdx.x, lane = t & 31, wid = t >> 5;
    int m0 = blockIdx.y * BM, n0 = blockIdx.x * BN;
    int warpM = (wid & 3) * 32, warpN = (wid >> 2) * 64;
    int row2 = t >> 1, half = t & 1;

    const uint4* sAh = (const uint4*)(g_Ahi  + (size_t)(m0 + row2) * NC);
    const uint4* sAl = (const uint4*)(g_Alo  + (size_t)(m0 + row2) * NC);
    const uint4* sBh = (const uint4*)(g_BhiT + (size_t)(n0 + row2) * NC);
    const uint4* sBl = (const uint4*)(g_BloT + (size_t)(n0 + row2) * NC);

    int srow = row2 * PITCH + half * 32;

    uint32_t sb0 = smem_u32(smq);
    uint32_t aoff = (uint32_t)((warpM + (lane & 15)) * PITCH + ((lane >> 4) << 4));
    uint32_t boff = (uint32_t)((warpN + (lane & 7) + ((lane >> 4) & 1) * 8) * PITCH
                               + (((lane >> 3) & 1) << 4));

    float acc[2][8][4];
    #pragma unroll
    for (int i = 0; i < 2; i++)
        #pragma unroll
        for (int j = 0; j < 8; j++)
            #pragma unroll
            for (int k = 0; k < 4; k++) acc[i][j][k] = 0.f;

    /* stage 0 preload */
    {
        int idx = half * 2;
        #pragma unroll
        for (int u = 0; u < 2; u++) {
            *(uint4*)(smq + 0*COMP_SZ + srow + 16*u) = sAh[idx + u];
            *(uint4*)(smq + 1*COMP_SZ + srow + 16*u) = sAl[idx + u];
            *(uint4*)(smq + 2*COMP_SZ + srow + 16*u) = sBh[idx + u];
            *(uint4*)(smq + 3*COMP_SZ + srow + 16*u) = sBl[idx + u];
        }
    }
    __syncthreads();

    for (int it = 0; it < NIT; it++) {
        /* fill next stage (independent buffer; sync at loop end) */
        if (it < NIT - 1) {
            int idx = (it + 1) * 4 + half * 2;
            unsigned char* sn = smq + ((it + 1) & 1) * STAGE_SZ;
            #pragma unroll
            for (int u = 0; u < 2; u++) {
                *(uint4*)(sn + 0*COMP_SZ + srow + 16*u) = sAh[idx + u];
                *(uint4*)(sn + 1*COMP_SZ + srow + 16*u) = sAl[idx + u];
                *(uint4*)(sn + 2*COMP_SZ + srow + 16*u) = sBh[idx + u];
                *(uint4*)(sn + 3*COMP_SZ + srow + 16*u) = sBl[idx + u];
            }
        }

        uint32_t st = sb0 + (uint32_t)((it & 1) * STAGE_SZ);
        uint32_t aAh = st + aoff;
        uint32_t aAl = st + 1*COMP_SZ + aoff;
        uint32_t aBh = st + 2*COMP_SZ + boff;
        uint32_t aBl = st + 3*COMP_SZ + boff;

        #pragma unroll
        for (int ko = 0; ko < 2; ko++) {
            uint32_t ah[2][4], al[2][4], bh[4][4], bl[4][4];
            #pragma unroll
            for (int mg = 0; mg < 2; mg++) {
                ldsm4(ah[mg], aAh + mg * (16 * PITCH) + ko * 32);
                ldsm4(al[mg], aAl + mg * (16 * PITCH) + ko * 32);
            }
            #pragma unroll
            for (int ng = 0; ng < 4; ng++) {
                ldsm4(bh[ng], aBh + ng * (16 * PITCH) + ko * 32);
                ldsm4(bl[ng], aBl + ng * (16 * PITCH) + ko * 32);
            }
            #pragma unroll
            for (int mg = 0; mg < 2; mg++)
                #pragma unroll
                for (int ng = 0; ng < 4; ng++)
                    #pragma unroll
                    for (int h = 0; h < 2; h++) {
                        float* d = acc[mg][ng * 2 + h];
                        /* smallest-magnitude terms first */
                        mma16816(d, al[mg], bh[ng][h*2], bh[ng][h*2+1]); /* lh */
                        mma16816(d, ah[mg], bl[ng][h*2], bl[ng][h*2+1]); /* hl */
                        mma16816(d, ah[mg], bh[ng][h*2], bh[ng][h*2+1]); /* hh */
                    }
        }
        __syncthreads();
    }

    /* epilogue: direct float2 stores */
    #pragma unroll
    for (int mg = 0; mg < 2; mg++)
        #pragma unroll
        for (int ng = 0; ng < 4; ng++)
            #pragma unroll
            for (int h = 0; h < 2; h++) {
                float* d = acc[mg][ng * 2 + h];
                int r = m0 + warpM + mg * 16 + (lane >> 2);
                int c = n0 + warpN + (ng * 2 + h) * 8 + (lane & 3) * 2;
                *(float2*)&C[(size_t)r * NC + c]       = make_float2(d[0], d[1]);
                *(float2*)&C[(size_t)(r + 8) * NC + c] = make_float2(d[2], d[3]);
            }
}

/* ------------------------------------------------------------------ */
/* attention: warp per token, 16 tokens/block (512 thr), K then V in smem */
__global__ void k_attn(float* __restrict__ out, const float* __restrict__ gain) {
    extern __shared__ float4 sKV[];            /* 32*256 float4 = 128KB */
    __shared__ float sKmag[SS];
    __shared__ float sMask[SS];
    int tid = threadIdx.x, warp = tid >> 5, lane = tid & 31;
    int tok0 = blockIdx.x * 16;
    int b = tok0 / LL;

    const float4* Ksrc = (const float4*)(out + OFF_NK + (size_t)b * SS * NC);
    for (int i = tid; i < SS * NC / 4; i += 512) sKV[i] = Ksrc[i];
    if (tid < SS) {
        sKmag[tid] = g_kmag[b * SS + tid];
        sMask[tid] = out[OFF_NM + b * SS + tid];
    }
    __syncthreads();

    int token = tok0 + warp;
    float4 q4[8];
    const float4* qrow = (const float4*)(out + (size_t)token * NC);
    #pragma unroll
    for (int i = 0; i < 8; i++) q4[i] = qrow[lane + 32 * i];

    float qs = 0.f;
    #pragma unroll
    for (int i = 0; i < 8; i++)
        qs += q4[i].x*q4[i].x + q4[i].y*q4[i].y + q4[i].z*q4[i].z + q4[i].w*q4[i].w;
    qs = wred(qs);
    float qmag = sqrtf(qs + EPSv);

    float myscore = -3e38f;
    for (int s = 0; s < SS; s++) {
        const float4* Kr = sKV + s * 256;
        float p = 0.f;
        #pragma unroll
        for (int i = 0; i < 8; i++) {
            float4 kv = Kr[lane + 32 * i];
            p += q4[i].x*kv.x + q4[i].y*kv.y + q4[i].z*kv.z + q4[i].w*kv.w;
        }
        p = wred(p);
        float sc = p / (qmag * sKmag[s] + EPSv);
        if (sMask[s] == 0.f) sc = -1e9f;
        if (lane == s) myscore = sc;
    }

    /* top-K with lowest-index tie break */
    float vcur = myscore;
    float topv[KK]; int topi[KK];
    #pragma unroll
    for (int j = 0; j < KK; j++) {
        float v = vcur; int idx = lane;
        #pragma unroll
        for (int o = 16; o; o >>= 1) {
            float v2 = __shfl_xor_sync(0xffffffffu, v, o);
            int   i2 = __shfl_xor_sync(0xffffffffu, idx, o);
            if (v2 > v || (v2 == v && i2 < idx)) { v = v2; idx = i2; }
        }
        topv[j] = v; topi[j] = idx;
        if (lane == idx) vcur = -INFINITY;
    }
    float w[KK], wsum = 0.f, mx = topv[0];
    #pragma unroll
    for (int j = 0; j < KK; j++) { w[j] = expf(topv[j] - mx); wsum += w[j]; }
    float winv = 1.f / wsum;

    __syncthreads();
    const float4* Vsrc = (const float4*)(out + OFF_NV + (size_t)b * SS * NC);
    for (int i = tid; i < SS * NC / 4; i += 512) sKV[i] = Vsrc[i];
    __syncthreads();

    float4 r[8];
    #pragma unroll
    for (int i = 0; i < 8; i++) r[i] = make_float4(0.f, 0.f, 0.f, 0.f);
    #pragma unroll
    for (int j = 0; j < KK; j++) {
        float a = w[j] * winv;
        const float4* Vr = sKV + topi[j] * 256;
        #pragma unroll
        for (int i = 0; i < 8; i++) {
            float4 vv = Vr[lane + 32 * i];
            r[i].x += a * vv.x; r[i].y += a * vv.y;
            r[i].z += a * vv.z; r[i].w += a * vv.w;
        }
    }
    float ssum = 0.f;
    #pragma unroll
    for (int i = 0; i < 8; i++)
        ssum += r[i].x*r[i].x + r[i].y*r[i].y + r[i].z*r[i].z + r[i].w*r[i].w;
    ssum = wred(ssum);
    float rinv = 1.f / sqrtf(ssum * (1.f / DIMC) + EPSv);

    const float2* g2 = (const float2*)gain;
    float4* orow = (float4*)(out + (size_t)token * NC);
    #pragma unroll
    for (int i = 0; i < 8; i++) {
        float2 g = g2[lane + 32 * i];
        float4 o;
        o.x = r[i].x * rinv * g.x; o.y = r[i].y * rinv * g.x;
        o.z = r[i].z * rinv * g.y; o.w = r[i].w * rinv * g.y;
        orow[lane + 32 * i] = o;
    }
}

/* ------------------------------------------------------------------ */
extern "C" void kernel_launch(void* const* d_in, const int* in_sizes, int n_in,
                              void* d_out, int out_size) {
    const float* z    = (const float*)d_in[0];
    const float* sk   = (const float*)d_in[1];
    const float* sv   = (const float*)d_in[2];
    const float* sm   = (const float*)d_in[3];
    const float* Wsr  = (const float*)d_in[4];
    const float* Wsi  = (const float*)d_in[5];
    const float* sb   = (const float*)d_in[6];
    const float* ns   = (const float*)d_in[7];
    const float* Wekr = (const float*)d_in[8];
    const float* Weki = (const float*)d_in[9];
    const float* Wevr = (const float*)d_in[10];
    const float* Wevi = (const float*)d_in[11];
    const float* Wrqr = (const float*)d_in[12];
    const float* Wrqi = (const float*)d_in[13];
    const float* gain = (const float*)d_in[14];
    float* out = (float*)d_out;

    static bool attr_done = false;
    if (!attr_done) {
        cudaFuncSetAttribute(k_attn, cudaFuncAttributeMaxDynamicSharedMemorySize, 131072);
        cudaFuncSetAttribute(k_qgemm_mma, cudaFuncAttributeMaxDynamicSharedMemorySize, QSMEM);
        attr_done = true;
    }

    /* qgemm at launch index 3 (deps: preA, build_bt only) so ncu samples it */
    k_preA<<<NT * NC / (256 * 8), 256>>>(z);
    k_build_bt<<<dim3(16, 16), 256>>>(Wrqr, Wrqi);
    k_stats<<<4096, 256>>>(z, Wsr, Wsi);
    k_qgemm_mma<<<dim3(NC / BN, NT / BM), 256, QSMEM>>>(out);
    k_salience<<<128, 256>>>(out, sb, ns);
    k_runs<<<Bb, 256>>>(out);
    k_evec<<<Bb * SS, 256>>>(z, out);
    k_eventkv<<<dim3(Bb, SS / 2), 512>>>(Wekr, Weki, Wevr, Wevi, sk, sv, out);
    k_mask<<<1, 256>>>(sm, out);
    k_attn<<<NT / 16, 512, 131072>>>(out, gain);
}

// round 7
// speedup vs baseline: 2.0173x; 1.2625x over previous
#include <cuda_runtime.h>
#include <cuda_fp16.h>
#include <math.h>
#include <stdint.h>

#define Bb   8
#define LL   4096
#define DIMC 512
#define SS   32
#define KK   8
#define NT   (Bb*LL)      /* 32768 tokens */
#define NC   (DIMC*2)     /* 1024 floats per token (interleaved r,i) */
#define THRv 0.5f
#define EPSv 1e-8f

/* output layout: concat(out, new_keys, new_values, new_mask, salience) */
#define OFF_OUT ((size_t)0)
#define OFF_NK  ((size_t)NT*NC)
#define OFF_NV  (OFF_NK + (size_t)Bb*SS*NC)
#define OFF_NM  (OFF_NV + (size_t)Bb*SS*NC)
#define OFF_SAL (OFF_NM + (size_t)Bb*SS)

/* scratch (device globals; no allocation allowed) */
__device__ float g_avg[NT];
__device__ float g_phase[NT];
__device__ float g_evec[Bb*SS*NC];
__device__ float g_emask[Bb*SS];
__device__ int   g_rs[Bb*SS];
__device__ int   g_re[Bb*SS];
__device__ float g_kmag[Bb*SS];
__device__ __half g_BhiT[NC*NC];          /* B^T fp16, [n][k], 2MB */
__device__ __half g_Ahi[(size_t)NT*NC];   /* z in fp16, 64MB */
__device__ float g_WrT[DIMC*DIMC];        /* W_rq_r transposed, 1MB */
__device__ float g_WiT[DIMC*DIMC];        /* W_rq_i transposed, 1MB */
__device__ float g_u[Bb*SS*NC];           /* u = B*kappa per slot, 1MB */
__device__ float g_qp[(size_t)NT*8];      /* qmag^2 partials per N-block, 1MB */

__device__ __forceinline__ float wred(float v) {
    #pragma unroll
    for (int o = 16; o; o >>= 1) v += __shfl_xor_sync(0xffffffffu, v, o);
    return v;
}

__device__ __forceinline__ uint32_t smem_u32(const void* p) {
    uint32_t a;
    asm("{ .reg .u64 t; cvta.to.shared.u64 t, %1; cvt.u32.u64 %0, t; }"
        : "=r"(a) : "l"(p));
    return a;
}

__device__ __forceinline__ void ldsm4(uint32_t* r, uint32_t addr) {
    asm volatile("ldmatrix.sync.aligned.m8n8.x4.shared.b16 {%0,%1,%2,%3}, [%4];"
        : "=r"(r[0]), "=r"(r[1]), "=r"(r[2]), "=r"(r[3]) : "r"(addr));
}

__device__ __forceinline__ void mma16816(float* d, const uint32_t* a,
                                         uint32_t b0, uint32_t b1) {
    asm volatile(
        "mma.sync.aligned.m16n8k16.row.col.f32.f16.f16.f32 "
        "{%0,%1,%2,%3}, {%4,%5,%6,%7}, {%8,%9}, {%0,%1,%2,%3};"
        : "+f"(d[0]), "+f"(d[1]), "+f"(d[2]), "+f"(d[3])
        : "r"(a[0]), "r"(a[1]), "r"(a[2]), "r"(a[3]), "r"(b0), "r"(b1));
}

/* ------------------------------------------------------------------ */
/* fused: per-token stats (avg mag, salience phase) + z->fp16 for qmag GEMM */
__global__ void k_stats(const float* __restrict__ z,
                        const float* __restrict__ Wsr,
                        const float* __restrict__ Wsi) {
    int gw = (blockIdx.x * blockDim.x + threadIdx.x) >> 5;
    int lane = threadIdx.x & 31;
    if (gw >= NT) return;
    const float4* z4 = (const float4*)(z + (size_t)gw * NC);
    __half2* arow = (__half2*)(g_Ahi + (size_t)gw * NC);
    float ms = 0.f, pr = 0.f, pi = 0.f;
    #pragma unroll
    for (int i = 0; i < 8; i++) {
        int p = lane + 32 * i;
        float4 v = z4[p];
        arow[2 * p]     = __floats2half2_rn(v.x, v.y);
        arow[2 * p + 1] = __floats2half2_rn(v.z, v.w);
        int d = 2 * p;
        ms += sqrtf(v.x*v.x + v.y*v.y + EPSv) + sqrtf(v.z*v.z + v.w*v.w + EPSv);
        float wr0 = Wsr[d], wi0 = Wsi[d], wr1 = Wsr[d+1], wi1 = Wsi[d+1];
        pr += v.x*wr0 - v.y*wi0 + v.z*wr1 - v.w*wi1;
        pi += v.x*wi0 + v.y*wr0 + v.z*wi1 + v.w*wr1;
    }
    ms = wred(ms); pr = wred(pr); pi = wred(pi);
    if (lane == 0) {
        g_avg[gw]   = ms * (1.f / DIMC);
        g_phase[gw] = sqrtf(pr*pr + pi*pi + EPSv);
    }
}

/* ------------------------------------------------------------------ */
/* Build transposed fp16 B (for qmag GEMM) and fp32 W transposes (for udot).
   BT[2e][2d]=Wr, BT[2e][2d+1]=-Wi, BT[2e+1][2d]=Wi, BT[2e+1][2d+1]=Wr. */
__global__ void k_build_bt(const float* __restrict__ Wr,
                           const float* __restrict__ Wi) {
    __shared__ float tr[32][33], ti[32][33];
    int tx = threadIdx.x & 31, ty = threadIdx.x >> 5;   /* 32 x 8 */
    int d0 = blockIdx.x * 32, e0 = blockIdx.y * 32;
    #pragma unroll
    for (int j = 0; j < 4; j++) {
        int d = d0 + ty + 8 * j;
        tr[ty + 8 * j][tx] = Wr[(size_t)d * DIMC + e0 + tx];
        ti[ty + 8 * j][tx] = Wi[(size_t)d * DIMC + e0 + tx];
    }
    __syncthreads();
    #pragma unroll
    for (int j = 0; j < 4; j++) {
        int e = e0 + ty + 8 * j;   /* column of W */
        int d = d0 + tx;           /* row of W    */
        float wr = tr[tx][ty + 8 * j], wi = ti[tx][ty + 8 * j];
        size_t r0 = (size_t)(2 * e) * NC, r1 = (size_t)(2 * e + 1) * NC;
        g_BhiT[r0 + 2*d]     = __float2half_rn(wr);
        g_BhiT[r0 + 2*d + 1] = __float2half_rn(-wi);
        g_BhiT[r1 + 2*d]     = __float2half_rn(wi);
        g_BhiT[r1 + 2*d + 1] = __float2half_rn(wr);
        g_WrT[(size_t)e * DIMC + d] = wr;
        g_WiT[(size_t)e * DIMC + d] = wi;
    }
}

/* ------------------------------------------------------------------ */
__global__ void k_salience(float* __restrict__ out,
                           const float* __restrict__ sb,
                           const float* __restrict__ ns) {
    int i = blockIdx.x * blockDim.x + threadIdx.x;
    if (i >= NT) return;
    int l = i & (LL - 1);
    float lm = 0.f;
    #pragma unroll
    for (int o = -2; o <= 2; o++) {
        int ll = l + o;
        if (ll >= 0 && ll < LL) lm += g_avg[i + o];
    }
    lm *= 0.2f;
    float x = g_phase[i] + (g_avg[i] - lm) * ns[0] + sb[0];
    out[OFF_SAL + i] = 1.f / (1.f + expf(-x));
}

/* per-batch run detection: first SS maximal runs of salience>THR */
__global__ void k_runs(const float* __restrict__ out) {
    int b = blockIdx.x, tid = threadIdx.x;
    const float* s = out + OFF_SAL + (size_t)b * LL;
    __shared__ int scnt[256];
    int l0 = tid * 16;
    bool prev0 = (l0 > 0) && (s[l0 - 1] > THRv);
    bool pa = prev0;
    int cnt = 0;
    for (int j = 0; j < 16; j++) {
        bool ab = s[l0 + j] > THRv;
        cnt += (ab && !pa);
        pa = ab;
    }
    scnt[tid] = cnt;
    if (tid < SS) { g_rs[b*SS+tid] = 0; g_re[b*SS+tid] = 0; g_emask[b*SS+tid] = 0.f; }
    __syncthreads();
    if (tid == 0) {
        int a = 0;
        for (int t = 0; t < 256; t++) { int c = scnt[t]; scnt[t] = a; a += c; }
    }
    __syncthreads();
    int e = scnt[tid];
    pa = prev0;
    for (int j = 0; j < 16; j++) {
        int l = l0 + j;
        bool ab = s[l] > THRv;
        if (ab && !pa) {
            if (e < SS) { g_rs[b*SS + e] = l; g_emask[b*SS + e] = 1.f; }
            e++;
        }
        if (ab && (e - 1) < SS) {
            bool nx = (l + 1 < LL) && (s[l + 1] > THRv);
            if (!nx) g_re[b*SS + (e - 1)] = l + 1;
        }
        pa = ab;
    }
}

/* event vectors: weighted mean of z over each run */
__global__ void k_evec(const float* __restrict__ z,
                       const float* __restrict__ out) {
    int bs = blockIdx.x, b = bs / SS;
    int rs = g_rs[bs], re = g_re[bs];
    const float* sal = out + OFF_SAL + (size_t)b * LL;
    int t = threadIdx.x;
    float a0 = 0.f, a1 = 0.f, a2 = 0.f, a3 = 0.f, den = 0.f;
    for (int l = rs; l < re; l++) {
        float w = sal[l];
        den += w;
        const float* zt = z + ((size_t)b * LL + l) * NC;
        a0 += w * zt[t];       a1 += w * zt[t + 256];
        a2 += w * zt[t + 512]; a3 += w * zt[t + 768];
    }
    float inv = 1.f / fmaxf(den, EPSv);
    float* ev = g_evec + (size_t)bs * NC;
    ev[t] = a0 * inv; ev[t + 256] = a1 * inv;
    ev[t + 512] = a2 * inv; ev[t + 768] = a3 * inv;
}

/* event keys/values projection + blend with slots + k_mag */
__global__ void k_eventkv(const float* __restrict__ Wekr, const float* __restrict__ Weki,
                          const float* __restrict__ Wevr, const float* __restrict__ Wevi,
                          const float* __restrict__ sk,   const float* __restrict__ svv,
                          float* __restrict__ out) {
    int b = blockIdx.x, sg = blockIdx.y;
    int e = threadIdx.x;
    __shared__ float sv[2][NC];
    __shared__ float wpart[2][16];
    for (int i = threadIdx.x; i < 2 * NC; i += 512)
        ((float*)sv)[i] = g_evec[(size_t)(b * SS + sg * 2) * NC + i];
    __syncthreads();
    float KR[2] = {0.f, 0.f}, KI[2] = {0.f, 0.f};
    float VR[2] = {0.f, 0.f}, VI[2] = {0.f, 0.f};
    for (int d = 0; d < DIMC; d++) {
        float wkr = Wekr[d * DIMC + e], wki = Weki[d * DIMC + e];
        float wvr = Wevr[d * DIMC + e], wvi = Wevi[d * DIMC + e];
        #pragma unroll
        for (int s2 = 0; s2 < 2; s2++) {
            float zr = sv[s2][2 * d], zi = sv[s2][2 * d + 1];
            KR[s2] += zr * wkr - zi * wki;
            KI[s2] += zr * wki + zi * wkr;
            VR[s2] += zr * wvr - zi * wvi;
            VI[s2] += zr * wvi + zi * wvr;
        }
    }
    int lane = e & 31, wid = e >> 5;
    #pragma unroll
    for (int s2 = 0; s2 < 2; s2++) {
        int bs = b * SS + sg * 2 + s2;
        float m = g_emask[bs];
        size_t off = (size_t)bs * NC + 2 * e;
        float nkr = m * KR[s2] + (1.f - m) * sk[off];
        float nki = m * KI[s2] + (1.f - m) * sk[off + 1];
        float nvr = m * VR[s2] + (1.f - m) * svv[off];
        float nvi = m * VI[s2] + (1.f - m) * svv[off + 1];
        out[OFF_NK + off] = nkr; out[OFF_NK + off + 1] = nki;
        out[OFF_NV + off] = nvr; out[OFF_NV + off + 1] = nvi;
        float p = wred(nkr * nkr + nki * nki);
        if (lane == 0) wpart[s2][wid] = p;
    }
    __syncthreads();
    if (threadIdx.x < 2) {
        float sum = 0.f;
        for (int i = 0; i < 16; i++) sum += wpart[threadIdx.x][i];
        g_kmag[b * SS + sg * 2 + threadIdx.x] = sqrtf(sum + EPSv);
    }
}

__global__ void k_mask(const float* __restrict__ slot_mask, float* __restrict__ out) {
    int i = threadIdx.x;
    if (i < Bb * SS) out[OFF_NM + i] = fminf(slot_mask[i] + g_emask[i], 1.f);
}

/* ------------------------------------------------------------------ */
/* u_{b,s} = B * kappa_{b,s}: per-token dot becomes z . u_s.
   ur_d = sum_j Wr[d][j]kr_j + Wi[d][j]ki_j ; ui_d = sum_j Wr[d][j]ki_j - Wi[d][j]kr_j
   grid (Bb, SS/8, 2), 256 threads (e-half). kappa staged in smem. */
__global__ void k_udot(const float* __restrict__ out) {
    __shared__ float ka[8][NC];   /* 32KB */
    int b = blockIdx.x, sg = blockIdx.y, eh = blockIdx.z;
    int tid = threadIdx.x;
    const float* ksrc = out + OFF_NK + (size_t)(b * SS + sg * 8) * NC;
    for (int i = tid; i < 8 * NC; i += 256)
        ((float*)ka)[i] = ksrc[i];
    __syncthreads();
    int e = eh * 256 + tid;
    float ur[8], ui[8];
    #pragma unroll
    for (int s = 0; s < 8; s++) { ur[s] = 0.f; ui[s] = 0.f; }
    for (int j = 0; j < DIMC; j++) {
        float wr = g_WrT[(size_t)j * DIMC + e];
        float wi = g_WiT[(size_t)j * DIMC + e];
        #pragma unroll
        for (int s = 0; s < 8; s++) {
            float2 kp = *(const float2*)&ka[s][2 * j];
            ur[s] += wr * kp.x + wi * kp.y;
            ui[s] += wr * kp.y - wi * kp.x;
        }
    }
    #pragma unroll
    for (int s = 0; s < 8; s++) {
        float* up = g_u + (size_t)(b * SS + sg * 8 + s) * NC;
        up[2 * e]     = ur[s];
        up[2 * e + 1] = ui[s];
    }
}

/* ------------------------------------------------------------------ */
/* single-term FP16 mma GEMM for qmag^2 only:
   qtil = Ahi * BhiT; per-row partial sum of qtil^2 -> g_qp[row][nblk].
   BM=128, BN=128, BK=32, 256 thr (8 warps, warp tile 32x64),
   80B pitch smem, double-buffered, 2 CTAs/SM. No C store. */
#define BM 128
#define BN 128
#define BKq 32
#define PITCH 80
#define COMP_SZ (BM * PITCH)          /* 10240 */
#define STAGE_SZ (2 * COMP_SZ)        /* 20480: Ah,Bh */
#define QSMEM (2 * STAGE_SZ)          /* 40960 */
#define NIT (NC / BKq)                /* 32 */

__global__ void __launch_bounds__(256, 2)
k_qgemm_mma() {
    extern __shared__ unsigned char smq[];
    __shared__ float qp_sm[2][BM];
    int t = threadIdx.x, lane = t & 31, wid = t >> 5;
    int m0 = blockIdx.y * BM, n0 = blockIdx.x * BN;
    int warpM = (wid & 3) * 32, warpN = (wid >> 2) * 64;
    int row2 = t >> 1, half = t & 1;

    const uint4* sAh = (const uint4*)(g_Ahi  + (size_t)(m0 + row2) * NC);
    const uint4* sBh = (const uint4*)(g_BhiT + (size_t)(n0 + row2) * NC);

    int srow = row2 * PITCH + half * 32;

    uint32_t sb0 = smem_u32(smq);
    uint32_t aoff = (uint32_t)((warpM + (lane & 15)) * PITCH + ((lane >> 4) << 4));
    uint32_t boff = (uint32_t)((warpN + (lane & 7) + ((lane >> 4) & 1) * 8) * PITCH
                               + (((lane >> 3) & 1) << 4));

    float acc[2][8][4];
    #pragma unroll
    for (int i = 0; i < 2; i++)
        #pragma unroll
        for (int j = 0; j < 8; j++)
            #pragma unroll
            for (int k = 0; k < 4; k++) acc[i][j][k] = 0.f;

    /* stage 0 preload */
    {
        int idx = half * 2;
        #pragma unroll
        for (int u = 0; u < 2; u++) {
            *(uint4*)(smq + srow + 16*u)           = sAh[idx + u];
            *(uint4*)(smq + COMP_SZ + srow + 16*u) = sBh[idx + u];
        }
    }
    __syncthreads();

    for (int it = 0; it < NIT; it++) {
        if (it < NIT - 1) {
            int idx = (it + 1) * 4 + half * 2;
            unsigned char* sn = smq + ((it + 1) & 1) * STAGE_SZ;
            #pragma unroll
            for (int u = 0; u < 2; u++) {
                *(uint4*)(sn + srow + 16*u)           = sAh[idx + u];
                *(uint4*)(sn + COMP_SZ + srow + 16*u) = sBh[idx + u];
            }
        }

        uint32_t st = sb0 + (uint32_t)((it & 1) * STAGE_SZ);
        uint32_t aAh = st + aoff;
        uint32_t aBh = st + COMP_SZ + boff;

        #pragma unroll
        for (int ko = 0; ko < 2; ko++) {
            uint32_t ah[2][4], bh[4][4];
            #pragma unroll
            for (int mg = 0; mg < 2; mg++)
                ldsm4(ah[mg], aAh + mg * (16 * PITCH) + ko * 32);
            #pragma unroll
            for (int ng = 0; ng < 4; ng++)
                ldsm4(bh[ng], aBh + ng * (16 * PITCH) + ko * 32);
            #pragma unroll
            for (int mg = 0; mg < 2; mg++)
                #pragma unroll
                for (int ng = 0; ng < 4; ng++)
                    #pragma unroll
                    for (int h = 0; h < 2; h++)
                        mma16816(acc[mg][ng * 2 + h], ah[mg],
                                 bh[ng][h*2], bh[ng][h*2+1]);
        }
        __syncthreads();
    }

    /* epilogue: per-row partial sums of qtil^2 (deterministic) */
    #pragma unroll
    for (int mg = 0; mg < 2; mg++) {
        float rp0 = 0.f, rp1 = 0.f;
        #pragma unroll
        for (int j = 0; j < 8; j++) {
            float* d = acc[mg][j];
            rp0 += d[0]*d[0] + d[1]*d[1];
            rp1 += d[2]*d[2] + d[3]*d[3];
        }
        rp0 += __shfl_xor_sync(0xffffffffu, rp0, 1);
        rp0 += __shfl_xor_sync(0xffffffffu, rp0, 2);
        rp1 += __shfl_xor_sync(0xffffffffu, rp1, 1);
        rp1 += __shfl_xor_sync(0xffffffffu, rp1, 2);
        if ((lane & 3) == 0) {
            int r = warpM + mg * 16 + (lane >> 2);
            qp_sm[wid >> 2][r]     = rp0;
            qp_sm[wid >> 2][r + 8] = rp1;
        }
    }
    __syncthreads();
    if (t < BM)
        g_qp[(size_t)(m0 + t) * 8 + blockIdx.x] = qp_sm[0][t] + qp_sm[1][t];
}

/* ------------------------------------------------------------------ */
/* attention: warp per token, 16 tokens/block; U then V staged in smem.
   dot = z . u_s ; qmag from g_qp partials. */
__global__ void k_attn(const float* __restrict__ z, float* __restrict__ out,
                       const float* __restrict__ gain) {
    extern __shared__ float4 sKV[];            /* 32*256 float4 = 128KB */
    __shared__ float sKmag[SS];
    __shared__ float sMask[SS];
    int tid = threadIdx.x, warp = tid >> 5, lane = tid & 31;
    int tok0 = blockIdx.x * 16;
    int b = tok0 / LL;

    const float4* Usrc = (const float4*)(g_u + (size_t)b * SS * NC);
    for (int i = tid; i < SS * NC / 4; i += 512) sKV[i] = Usrc[i];
    if (tid < SS) {
        sKmag[tid] = g_kmag[b * SS + tid];
        sMask[tid] = out[OFF_NM + b * SS + tid];
    }
    __syncthreads();

    int token = tok0 + warp;
    float4 q4[8];
    const float4* zrow = (const float4*)(z + (size_t)token * NC);
    #pragma unroll
    for (int i = 0; i < 8; i++) q4[i] = zrow[lane + 32 * i];

    float qp = (lane < 8) ? g_qp[(size_t)token * 8 + lane] : 0.f;
    qp = wred(qp);
    float qmag = sqrtf(qp + EPSv);

    float myscore = -3e38f;
    for (int s = 0; s < SS; s++) {
        const float4* Ur = sKV + s * 256;
        float p = 0.f;
        #pragma unroll
        for (int i = 0; i < 8; i++) {
            float4 uv = Ur[lane + 32 * i];
            p += q4[i].x*uv.x + q4[i].y*uv.y + q4[i].z*uv.z + q4[i].w*uv.w;
        }
        p = wred(p);
        float sc = p / (qmag * sKmag[s] + EPSv);
        if (sMask[s] == 0.f) sc = -1e9f;
        if (lane == s) myscore = sc;
    }

    /* top-K with lowest-index tie break */
    float vcur = myscore;
    float topv[KK]; int topi[KK];
    #pragma unroll
    for (int j = 0; j < KK; j++) {
        float v = vcur; int idx = lane;
        #pragma unroll
        for (int o = 16; o; o >>= 1) {
            float v2 = __shfl_xor_sync(0xffffffffu, v, o);
            int   i2 = __shfl_xor_sync(0xffffffffu, idx, o);
            if (v2 > v || (v2 == v && i2 < idx)) { v = v2; idx = i2; }
        }
        topv[j] = v; topi[j] = idx;
        if (lane == idx) vcur = -INFINITY;
    }
    float w[KK], wsum = 0.f, mx = topv[0];
    #pragma unroll
    for (int j = 0; j < KK; j++) { w[j] = expf(topv[j] - mx); wsum += w[j]; }
    float winv = 1.f / wsum;

    __syncthreads();
    const float4* Vsrc = (const float4*)(out + OFF_NV + (size_t)b * SS * NC);
    for (int i = tid; i < SS * NC / 4; i += 512) sKV[i] = Vsrc[i];
    __syncthreads();

    float4 r[8];
    #pragma unroll
    for (int i = 0; i < 8; i++) r[i] = make_float4(0.f, 0.f, 0.f, 0.f);
    #pragma unroll
    for (int j = 0; j < KK; j++) {
        float a = w[j] * winv;
        const float4* Vr = sKV + topi[j] * 256;
        #pragma unroll
        for (int i = 0; i < 8; i++) {
            float4 vv = Vr[lane + 32 * i];
            r[i].x += a * vv.x; r[i].y += a * vv.y;
            r[i].z += a * vv.z; r[i].w += a * vv.w;
        }
    }
    float ssum = 0.f;
    #pragma unroll
    for (int i = 0; i < 8; i++)
        ssum += r[i].x*r[i].x + r[i].y*r[i].y + r[i].z*r[i].z + r[i].w*r[i].w;
    ssum = wred(ssum);
    float rinv = 1.f / sqrtf(ssum * (1.f / DIMC) + EPSv);

    const float2* g2 = (const float2*)gain;
    float4* orow = (float4*)(out + (size_t)token * NC);
    #pragma unroll
    for (int i = 0; i < 8; i++) {
        float2 g = g2[lane + 32 * i];
        float4 o;
        o.x = r[i].x * rinv * g.x; o.y = r[i].y * rinv * g.x;
        o.z = r[i].z * rinv * g.y; o.w = r[i].w * rinv * g.y;
        orow[lane + 32 * i] = o;
    }
}

/* ------------------------------------------------------------------ */
extern "C" void kernel_launch(void* const* d_in, const int* in_sizes, int n_in,
                              void* d_out, int out_size) {
    const float* z    = (const float*)d_in[0];
    const float* sk   = (const float*)d_in[1];
    const float* sv   = (const float*)d_in[2];
    const float* sm   = (const float*)d_in[3];
    const float* Wsr  = (const float*)d_in[4];
    const float* Wsi  = (const float*)d_in[5];
    const float* sb   = (const float*)d_in[6];
    const float* ns   = (const float*)d_in[7];
    const float* Wekr = (const float*)d_in[8];
    const float* Weki = (const float*)d_in[9];
    const float* Wevr = (const float*)d_in[10];
    const float* Wevi = (const float*)d_in[11];
    const float* Wrqr = (const float*)d_in[12];
    const float* Wrqi = (const float*)d_in[13];
    const float* gain = (const float*)d_in[14];
    float* out = (float*)d_out;

    static bool attr_done = false;
    if (!attr_done) {
        cudaFuncSetAttribute(k_attn, cudaFuncAttributeMaxDynamicSharedMemorySize, 131072);
        cudaFuncSetAttribute(k_qgemm_mma, cudaFuncAttributeMaxDynamicSharedMemorySize, QSMEM);
        attr_done = true;
    }

    k_stats<<<4096, 256>>>(z, Wsr, Wsi);               /* idx 0 */
    k_build_bt<<<dim3(16, 16), 256>>>(Wrqr, Wrqi);     /* idx 1 */
    k_salience<<<128, 256>>>(out, sb, ns);             /* idx 2 */
    k_qgemm_mma<<<dim3(NC / BN, NT / BM), 256, QSMEM>>>();  /* idx 3: ncu */
    k_runs<<<Bb, 256>>>(out);
    k_evec<<<Bb * SS, 256>>>(z, out);
    k_eventkv<<<dim3(Bb, SS / 2), 512>>>(Wekr, Weki, Wevr, Wevi, sk, sv, out);
    k_udot<<<dim3(Bb, SS / 8, 2), 256>>>(out);
    k_mask<<<1, 256>>>(sm, out);
    k_attn<<<NT / 16, 512, 131072>>>(z, out, gain);
}

// round 8
// speedup vs baseline: 2.2486x; 1.1147x over previous
#include <cuda_runtime.h>
#include <cuda_fp16.h>
#include <math.h>
#include <stdint.h>

#define Bb   8
#define LL   4096
#define DIMC 512
#define SS   32
#define KK   8
#define NT   (Bb*LL)      /* 32768 tokens */
#define NC   (DIMC*2)     /* 1024 floats per token (interleaved r,i) */
#define THRv 0.5f
#define EPSv 1e-8f

/* output layout: concat(out, new_keys, new_values, new_mask, salience) */
#define OFF_OUT ((size_t)0)
#define OFF_NK  ((size_t)NT*NC)
#define OFF_NV  (OFF_NK + (size_t)Bb*SS*NC)
#define OFF_NM  (OFF_NV + (size_t)Bb*SS*NC)
#define OFF_SAL (OFF_NM + (size_t)Bb*SS)

/* scratch (device globals; no allocation allowed) */
__device__ float g_avg[NT];
__device__ float g_phase[NT];
__device__ float g_evec[Bb*SS*NC];
__device__ float g_emask[Bb*SS];
__device__ int   g_rs[Bb*SS];
__device__ int   g_re[Bb*SS];
__device__ float g_kmag[Bb*SS];
__device__ __half g_BhiT[NC*NC];          /* B^T fp16, [n][k], 2MB */
__device__ __half g_Ahi[(size_t)NT*NC];   /* z in fp16, 64MB */
__device__ float g_WrT[DIMC*DIMC];        /* W_rq_r transposed, 1MB */
__device__ float g_WiT[DIMC*DIMC];        /* W_rq_i transposed, 1MB */
__device__ float g_u[Bb*SS*NC];           /* u = B*kappa per slot, 1MB */
__device__ float g_qp[(size_t)NT*8];      /* qmag^2 partials per N-block, 1MB */

__device__ __forceinline__ float wred(float v) {
    #pragma unroll
    for (int o = 16; o; o >>= 1) v += __shfl_xor_sync(0xffffffffu, v, o);
    return v;
}

/* fast approx math (1 MUFU each; max rel err ~2^-22) */
__device__ __forceinline__ float fsqrt(float x) {
    float y; asm("sqrt.approx.f32 %0, %1;" : "=f"(y) : "f"(x)); return y;
}
__device__ __forceinline__ float frcp(float x) {
    float y; asm("rcp.approx.f32 %0, %1;" : "=f"(y) : "f"(x)); return y;
}
__device__ __forceinline__ float frsqrt(float x) {
    float y; asm("rsqrt.approx.f32 %0, %1;" : "=f"(y) : "f"(x)); return y;
}

__device__ __forceinline__ uint32_t smem_u32(const void* p) {
    uint32_t a;
    asm("{ .reg .u64 t; cvta.to.shared.u64 t, %1; cvt.u32.u64 %0, t; }"
        : "=r"(a) : "l"(p));
    return a;
}

__device__ __forceinline__ void ldsm4(uint32_t* r, uint32_t addr) {
    asm volatile("ldmatrix.sync.aligned.m8n8.x4.shared.b16 {%0,%1,%2,%3}, [%4];"
        : "=r"(r[0]), "=r"(r[1]), "=r"(r[2]), "=r"(r[3]) : "r"(addr));
}

__device__ __forceinline__ void mma16816(float* d, const uint32_t* a,
                                         uint32_t b0, uint32_t b1) {
    asm volatile(
        "mma.sync.aligned.m16n8k16.row.col.f32.f16.f16.f32 "
        "{%0,%1,%2,%3}, {%4,%5,%6,%7}, {%8,%9}, {%0,%1,%2,%3};"
        : "+f"(d[0]), "+f"(d[1]), "+f"(d[2]), "+f"(d[3])
        : "r"(a[0]), "r"(a[1]), "r"(a[2]), "r"(a[3]), "r"(b0), "r"(b1));
}

#define CP16(dst, src) \
    asm volatile("cp.async.cg.shared.global [%0], [%1], 16;" \
                 :: "r"(dst), "l"(src) : "memory")
#define CP_COMMIT() asm volatile("cp.async.commit_group;" ::: "memory")
#define CP_WAIT1()  asm volatile("cp.async.wait_group 1;" ::: "memory")

/* ------------------------------------------------------------------ */
/* fused: per-token stats (avg mag, salience phase) + z->fp16 for qmag GEMM */
__global__ void k_stats(const float* __restrict__ z,
                        const float* __restrict__ Wsr,
                        const float* __restrict__ Wsi) {
    int gw = (blockIdx.x * blockDim.x + threadIdx.x) >> 5;
    int lane = threadIdx.x & 31;
    if (gw >= NT) return;
    const float4* z4 = (const float4*)(z + (size_t)gw * NC);
    __half2* arow = (__half2*)(g_Ahi + (size_t)gw * NC);
    float ms = 0.f, pr = 0.f, pi = 0.f;
    #pragma unroll
    for (int i = 0; i < 8; i++) {
        int p = lane + 32 * i;
        float4 v = z4[p];
        arow[2 * p]     = __floats2half2_rn(v.x, v.y);
        arow[2 * p + 1] = __floats2half2_rn(v.z, v.w);
        int d = 2 * p;
        ms += fsqrt(v.x*v.x + v.y*v.y + EPSv) + fsqrt(v.z*v.z + v.w*v.w + EPSv);
        float wr0 = Wsr[d], wi0 = Wsi[d], wr1 = Wsr[d+1], wi1 = Wsi[d+1];
        pr += v.x*wr0 - v.y*wi0 + v.z*wr1 - v.w*wi1;
        pi += v.x*wi0 + v.y*wr0 + v.z*wi1 + v.w*wr1;
    }
    ms = wred(ms); pr = wred(pr); pi = wred(pi);
    if (lane == 0) {
        g_avg[gw]   = ms * (1.f / DIMC);
        g_phase[gw] = fsqrt(pr*pr + pi*pi + EPSv);
    }
}

/* ------------------------------------------------------------------ */
/* Build transposed fp16 B (for qmag GEMM) and fp32 W transposes (for udot). */
__global__ void k_build_bt(const float* __restrict__ Wr,
                           const float* __restrict__ Wi) {
    __shared__ float tr[32][33], ti[32][33];
    int tx = threadIdx.x & 31, ty = threadIdx.x >> 5;   /* 32 x 8 */
    int d0 = blockIdx.x * 32, e0 = blockIdx.y * 32;
    #pragma unroll
    for (int j = 0; j < 4; j++) {
        int d = d0 + ty + 8 * j;
        tr[ty + 8 * j][tx] = Wr[(size_t)d * DIMC + e0 + tx];
        ti[ty + 8 * j][tx] = Wi[(size_t)d * DIMC + e0 + tx];
    }
    __syncthreads();
    #pragma unroll
    for (int j = 0; j < 4; j++) {
        int e = e0 + ty + 8 * j;
        int d = d0 + tx;
        float wr = tr[tx][ty + 8 * j], wi = ti[tx][ty + 8 * j];
        size_t r0 = (size_t)(2 * e) * NC, r1 = (size_t)(2 * e + 1) * NC;
        g_BhiT[r0 + 2*d]     = __float2half_rn(wr);
        g_BhiT[r0 + 2*d + 1] = __float2half_rn(-wi);
        g_BhiT[r1 + 2*d]     = __float2half_rn(wi);
        g_BhiT[r1 + 2*d + 1] = __float2half_rn(wr);
        g_WrT[(size_t)e * DIMC + d] = wr;
        g_WiT[(size_t)e * DIMC + d] = wi;
    }
}

/* ------------------------------------------------------------------ */
__global__ void k_salience(float* __restrict__ out,
                           const float* __restrict__ sb,
                           const float* __restrict__ ns) {
    int i = blockIdx.x * blockDim.x + threadIdx.x;
    if (i >= NT) return;
    int l = i & (LL - 1);
    float lm = 0.f;
    #pragma unroll
    for (int o = -2; o <= 2; o++) {
        int ll = l + o;
        if (ll >= 0 && ll < LL) lm += g_avg[i + o];
    }
    lm *= 0.2f;
    float x = g_phase[i] + (g_avg[i] - lm) * ns[0] + sb[0];
    out[OFF_SAL + i] = frcp(1.f + __expf(-x));
}

/* per-batch run detection: first SS maximal runs of salience>THR */
__global__ void k_runs(const float* __restrict__ out) {
    int b = blockIdx.x, tid = threadIdx.x;
    const float* s = out + OFF_SAL + (size_t)b * LL;
    __shared__ int scnt[256];
    int l0 = tid * 16;
    bool prev0 = (l0 > 0) && (s[l0 - 1] > THRv);
    bool pa = prev0;
    int cnt = 0;
    for (int j = 0; j < 16; j++) {
        bool ab = s[l0 + j] > THRv;
        cnt += (ab && !pa);
        pa = ab;
    }
    scnt[tid] = cnt;
    if (tid < SS) { g_rs[b*SS+tid] = 0; g_re[b*SS+tid] = 0; g_emask[b*SS+tid] = 0.f; }
    __syncthreads();
    if (tid == 0) {
        int a = 0;
        for (int t = 0; t < 256; t++) { int c = scnt[t]; scnt[t] = a; a += c; }
    }
    __syncthreads();
    int e = scnt[tid];
    pa = prev0;
    for (int j = 0; j < 16; j++) {
        int l = l0 + j;
        bool ab = s[l] > THRv;
        if (ab && !pa) {
            if (e < SS) { g_rs[b*SS + e] = l; g_emask[b*SS + e] = 1.f; }
            e++;
        }
        if (ab && (e - 1) < SS) {
            bool nx = (l + 1 < LL) && (s[l + 1] > THRv);
            if (!nx) g_re[b*SS + (e - 1)] = l + 1;
        }
        pa = ab;
    }
}

/* event vectors: weighted mean of z over each run */
__global__ void k_evec(const float* __restrict__ z,
                       const float* __restrict__ out) {
    int bs = blockIdx.x, b = bs / SS;
    int rs = g_rs[bs], re = g_re[bs];
    const float* sal = out + OFF_SAL + (size_t)b * LL;
    int t = threadIdx.x;
    float a0 = 0.f, a1 = 0.f, a2 = 0.f, a3 = 0.f, den = 0.f;
    for (int l = rs; l < re; l++) {
        float w = sal[l];
        den += w;
        const float* zt = z + ((size_t)b * LL + l) * NC;
        a0 += w * zt[t];       a1 += w * zt[t + 256];
        a2 += w * zt[t + 512]; a3 += w * zt[t + 768];
    }
    float inv = frcp(fmaxf(den, EPSv));
    float* ev = g_evec + (size_t)bs * NC;
    ev[t] = a0 * inv; ev[t + 256] = a1 * inv;
    ev[t + 512] = a2 * inv; ev[t + 768] = a3 * inv;
}

/* event keys/values projection + blend with slots + k_mag */
__global__ void k_eventkv(const float* __restrict__ Wekr, const float* __restrict__ Weki,
                          const float* __restrict__ Wevr, const float* __restrict__ Wevi,
                          const float* __restrict__ sk,   const float* __restrict__ svv,
                          float* __restrict__ out) {
    int b = blockIdx.x, sg = blockIdx.y;
    int e = threadIdx.x;
    __shared__ float sv[2][NC];
    __shared__ float wpart[2][16];
    for (int i = threadIdx.x; i < 2 * NC; i += 512)
        ((float*)sv)[i] = g_evec[(size_t)(b * SS + sg * 2) * NC + i];
    __syncthreads();
    float KR[2] = {0.f, 0.f}, KI[2] = {0.f, 0.f};
    float VR[2] = {0.f, 0.f}, VI[2] = {0.f, 0.f};
    for (int d = 0; d < DIMC; d++) {
        float wkr = Wekr[d * DIMC + e], wki = Weki[d * DIMC + e];
        float wvr = Wevr[d * DIMC + e], wvi = Wevi[d * DIMC + e];
        #pragma unroll
        for (int s2 = 0; s2 < 2; s2++) {
            float zr = sv[s2][2 * d], zi = sv[s2][2 * d + 1];
            KR[s2] += zr * wkr - zi * wki;
            KI[s2] += zr * wki + zi * wkr;
            VR[s2] += zr * wvr - zi * wvi;
            VI[s2] += zr * wvi + zi * wvr;
        }
    }
    int lane = e & 31, wid = e >> 5;
    #pragma unroll
    for (int s2 = 0; s2 < 2; s2++) {
        int bs = b * SS + sg * 2 + s2;
        float m = g_emask[bs];
        size_t off = (size_t)bs * NC + 2 * e;
        float nkr = m * KR[s2] + (1.f - m) * sk[off];
        float nki = m * KI[s2] + (1.f - m) * sk[off + 1];
        float nvr = m * VR[s2] + (1.f - m) * svv[off];
        float nvi = m * VI[s2] + (1.f - m) * svv[off + 1];
        out[OFF_NK + off] = nkr; out[OFF_NK + off + 1] = nki;
        out[OFF_NV + off] = nvr; out[OFF_NV + off + 1] = nvi;
        float p = wred(nkr * nkr + nki * nki);
        if (lane == 0) wpart[s2][wid] = p;
    }
    __syncthreads();
    if (threadIdx.x < 2) {
        float sum = 0.f;
        for (int i = 0; i < 16; i++) sum += wpart[threadIdx.x][i];
        g_kmag[b * SS + sg * 2 + threadIdx.x] = fsqrt(sum + EPSv);
    }
}

__global__ void k_mask(const float* __restrict__ slot_mask, float* __restrict__ out) {
    int i = threadIdx.x;
    if (i < Bb * SS) out[OFF_NM + i] = fminf(slot_mask[i] + g_emask[i], 1.f);
}

/* ------------------------------------------------------------------ */
/* u_{b,s} = B * kappa_{b,s} */
__global__ void k_udot(const float* __restrict__ out) {
    __shared__ float ka[8][NC];
    int b = blockIdx.x, sg = blockIdx.y, eh = blockIdx.z;
    int tid = threadIdx.x;
    const float* ksrc = out + OFF_NK + (size_t)(b * SS + sg * 8) * NC;
    for (int i = tid; i < 8 * NC; i += 256)
        ((float*)ka)[i] = ksrc[i];
    __syncthreads();
    int e = eh * 256 + tid;
    float ur[8], ui[8];
    #pragma unroll
    for (int s = 0; s < 8; s++) { ur[s] = 0.f; ui[s] = 0.f; }
    for (int j = 0; j < DIMC; j++) {
        float wr = g_WrT[(size_t)j * DIMC + e];
        float wi = g_WiT[(size_t)j * DIMC + e];
        #pragma unroll
        for (int s = 0; s < 8; s++) {
            float2 kp = *(const float2*)&ka[s][2 * j];
            ur[s] += wr * kp.x + wi * kp.y;
            ui[s] += wr * kp.y - wi * kp.x;
        }
    }
    #pragma unroll
    for (int s = 0; s < 8; s++) {
        float* up = g_u + (size_t)(b * SS + sg * 8 + s) * NC;
        up[2 * e]     = ur[s];
        up[2 * e + 1] = ui[s];
    }
}

/* ------------------------------------------------------------------ */
/* single-term FP16 mma GEMM for qmag^2, cp.async 3-stage pipeline.
   BM=128, BN=128, BK=32, 256 thr (8 warps, warp tile 32x64), 80B pitch. */
#define BM 128
#define BN 128
#define BKq 32
#define PITCH 80
#define COMP_SZ (BM * PITCH)          /* 10240 */
#define STAGE_SZ (2 * COMP_SZ)        /* 20480: Ah,Bh */
#define NSTG 3
#define QSMEM (NSTG * STAGE_SZ)       /* 61440 */
#define NIT (NC / BKq)                /* 32 */

__global__ void __launch_bounds__(256, 2)
k_qgemm_mma() {
    extern __shared__ unsigned char smq[];
    __shared__ float qp_sm[2][BM];
    int t = threadIdx.x, lane = t & 31, wid = t >> 5;
    int m0 = blockIdx.y * BM, n0 = blockIdx.x * BN;
    int warpM = (wid & 3) * 32, warpN = (wid >> 2) * 64;
    int row2 = t >> 1, half = t & 1;

    const uint4* sAh = (const uint4*)(g_Ahi  + (size_t)(m0 + row2) * NC);
    const uint4* sBh = (const uint4*)(g_BhiT + (size_t)(n0 + row2) * NC);

    int srow = row2 * PITCH + half * 32;
    uint32_t sb0 = smem_u32(smq);
    uint32_t dstA = sb0 + (uint32_t)srow;
    uint32_t dstB = sb0 + (uint32_t)(COMP_SZ + srow);

    uint32_t aoff = (uint32_t)((warpM + (lane & 15)) * PITCH + ((lane >> 4) << 4));
    uint32_t boff = (uint32_t)((warpN + (lane & 7) + ((lane >> 4) & 1) * 8) * PITCH
                               + (((lane >> 3) & 1) << 4));

    float acc[2][8][4];
    #pragma unroll
    for (int i = 0; i < 2; i++)
        #pragma unroll
        for (int j = 0; j < 8; j++)
            #pragma unroll
            for (int k = 0; k < 4; k++) acc[i][j][k] = 0.f;

    /* prologue: stages 0,1 */
    #pragma unroll
    for (int s = 0; s < 2; s++) {
        const uint4* a = sAh + s * 4 + half * 2;
        const uint4* b = sBh + s * 4 + half * 2;
        uint32_t off = (uint32_t)(s * STAGE_SZ);
        CP16(dstA + off, a);       CP16(dstA + off + 16, a + 1);
        CP16(dstB + off, b);       CP16(dstB + off + 16, b + 1);
        CP_COMMIT();
    }

    for (int it = 0; it < NIT; it++) {
        int stg = it % NSTG;
        CP_WAIT1();
        __syncthreads();

        uint32_t st = sb0 + (uint32_t)(stg * STAGE_SZ);
        uint32_t aAh = st + aoff;
        uint32_t aBh = st + COMP_SZ + boff;

        #pragma unroll
        for (int ko = 0; ko < 2; ko++) {
            uint32_t ah[2][4], bh[4][4];
            #pragma unroll
            for (int mg = 0; mg < 2; mg++)
                ldsm4(ah[mg], aAh + mg * (16 * PITCH) + ko * 32);
            #pragma unroll
            for (int ng = 0; ng < 4; ng++)
                ldsm4(bh[ng], aBh + ng * (16 * PITCH) + ko * 32);
            #pragma unroll
            for (int mg = 0; mg < 2; mg++)
                #pragma unroll
                for (int ng = 0; ng < 4; ng++)
                    #pragma unroll
                    for (int h = 0; h < 2; h++)
                        mma16816(acc[mg][ng * 2 + h], ah[mg],
                                 bh[ng][h*2], bh[ng][h*2+1]);
        }

        if (it + 2 < NIT) {
            int ns = (it + 2) % NSTG;
            const uint4* a = sAh + (it + 2) * 4 + half * 2;
            const uint4* b = sBh + (it + 2) * 4 + half * 2;
            uint32_t off = (uint32_t)(ns * STAGE_SZ);
            CP16(dstA + off, a);       CP16(dstA + off + 16, a + 1);
            CP16(dstB + off, b);       CP16(dstB + off + 16, b + 1);
        }
        CP_COMMIT();
    }

    /* epilogue: per-row partial sums of qtil^2 (deterministic) */
    #pragma unroll
    for (int mg = 0; mg < 2; mg++) {
        float rp0 = 0.f, rp1 = 0.f;
        #pragma unroll
        for (int j = 0; j < 8; j++) {
            float* d = acc[mg][j];
            rp0 += d[0]*d[0] + d[1]*d[1];
            rp1 += d[2]*d[2] + d[3]*d[3];
        }
        rp0 += __shfl_xor_sync(0xffffffffu, rp0, 1);
        rp0 += __shfl_xor_sync(0xffffffffu, rp0, 2);
        rp1 += __shfl_xor_sync(0xffffffffu, rp1, 1);
        rp1 += __shfl_xor_sync(0xffffffffu, rp1, 2);
        if ((lane & 3) == 0) {
            int r = warpM + mg * 16 + (lane >> 2);
            qp_sm[wid >> 2][r]     = rp0;
            qp_sm[wid >> 2][r + 8] = rp1;
        }
    }
    __syncthreads();
    if (t < BM)
        g_qp[(size_t)(m0 + t) * 8 + blockIdx.x] = qp_sm[0][t] + qp_sm[1][t];
}

/* ------------------------------------------------------------------ */
/* attention: warp per token, 16 tokens/block; U then V staged in smem. */
__global__ void k_attn(const float* __restrict__ z, float* __restrict__ out,
                       const float* __restrict__ gain) {
    extern __shared__ float4 sKV[];            /* 32*256 float4 = 128KB */
    __shared__ float sKmag[SS];
    __shared__ float sMask[SS];
    int tid = threadIdx.x, warp = tid >> 5, lane = tid & 31;
    int tok0 = blockIdx.x * 16;
    int b = tok0 / LL;

    const float4* Usrc = (const float4*)(g_u + (size_t)b * SS * NC);
    for (int i = tid; i < SS * NC / 4; i += 512) sKV[i] = Usrc[i];
    if (tid < SS) {
        sKmag[tid] = g_kmag[b * SS + tid];
        sMask[tid] = out[OFF_NM + b * SS + tid];
    }
    __syncthreads();

    int token = tok0 + warp;
    float4 q4[8];
    const float4* zrow = (const float4*)(z + (size_t)token * NC);
    #pragma unroll
    for (int i = 0; i < 8; i++) q4[i] = zrow[lane + 32 * i];

    float qp = (lane < 8) ? g_qp[(size_t)token * 8 + lane] : 0.f;
    qp = wred(qp);
    float qmag = fsqrt(qp + EPSv);

    float myscore = -3e38f;
    for (int s = 0; s < SS; s++) {
        const float4* Ur = sKV + s * 256;
        float p = 0.f;
        #pragma unroll
        for (int i = 0; i < 8; i++) {
            float4 uv = Ur[lane + 32 * i];
            p += q4[i].x*uv.x + q4[i].y*uv.y + q4[i].z*uv.z + q4[i].w*uv.w;
        }
        p = wred(p);
        float sc = p * frcp(qmag * sKmag[s] + EPSv);
        if (sMask[s] == 0.f) sc = -1e9f;
        if (lane == s) myscore = sc;
    }

    /* top-K with lowest-index tie break */
    float vcur = myscore;
    float topv[KK]; int topi[KK];
    #pragma unroll
    for (int j = 0; j < KK; j++) {
        float v = vcur; int idx = lane;
        #pragma unroll
        for (int o = 16; o; o >>= 1) {
            float v2 = __shfl_xor_sync(0xffffffffu, v, o);
            int   i2 = __shfl_xor_sync(0xffffffffu, idx, o);
            if (v2 > v || (v2 == v && i2 < idx)) { v = v2; idx = i2; }
        }
        topv[j] = v; topi[j] = idx;
        if (lane == idx) vcur = -INFINITY;
    }
    float w[KK], wsum = 0.f, mx = topv[0];
    #pragma unroll
    for (int j = 0; j < KK; j++) { w[j] = __expf(topv[j] - mx); wsum += w[j]; }
    float winv = frcp(wsum);

    __syncthreads();
    const float4* Vsrc = (const float4*)(out + OFF_NV + (size_t)b * SS * NC);
    for (int i = tid; i < SS * NC / 4; i += 512) sKV[i] = Vsrc[i];
    __syncthreads();

    float4 r[8];
    #pragma unroll
    for (int i = 0; i < 8; i++) r[i] = make_float4(0.f, 0.f, 0.f, 0.f);
    #pragma unroll
    for (int j = 0; j < KK; j++) {
        float a = w[j] * winv;
        const float4* Vr = sKV + topi[j] * 256;
        #pragma unroll
        for (int i = 0; i < 8; i++) {
            float4 vv = Vr[lane + 32 * i];
            r[i].x += a * vv.x; r[i].y += a * vv.y;
            r[i].z += a * vv.z; r[i].w += a * vv.w;
        }
    }
    float ssum = 0.f;
    #pragma unroll
    for (int i = 0; i < 8; i++)
        ssum += r[i].x*r[i].x + r[i].y*r[i].y + r[i].z*r[i].z + r[i].w*r[i].w;
    ssum = wred(ssum);
    float rinv = frsqrt(ssum * (1.f / DIMC) + EPSv);

    const float2* g2 = (const float2*)gain;
    float4* orow = (float4*)(out + (size_t)token * NC);
    #pragma unroll
    for (int i = 0; i < 8; i++) {
        float2 g = g2[lane + 32 * i];
        float4 o;
        o.x = r[i].x * rinv * g.x; o.y = r[i].y * rinv * g.x;
        o.z = r[i].z * rinv * g.y; o.w = r[i].w * rinv * g.y;
        orow[lane + 32 * i] = o;
    }
}

/* ------------------------------------------------------------------ */
extern "C" void kernel_launch(void* const* d_in, const int* in_sizes, int n_in,
                              void* d_out, int out_size) {
    const float* z    = (const float*)d_in[0];
    const float* sk   = (const float*)d_in[1];
    const float* sv   = (const float*)d_in[2];
    const float* sm   = (const float*)d_in[3];
    const float* Wsr  = (const float*)d_in[4];
    const float* Wsi  = (const float*)d_in[5];
    const float* sb   = (const float*)d_in[6];
    const float* ns   = (const float*)d_in[7];
    const float* Wekr = (const float*)d_in[8];
    const float* Weki = (const float*)d_in[9];
    const float* Wevr = (const float*)d_in[10];
    const float* Wevi = (const float*)d_in[11];
    const float* Wrqr = (const float*)d_in[12];
    const float* Wrqi = (const float*)d_in[13];
    const float* gain = (const float*)d_in[14];
    float* out = (float*)d_out;

    static bool attr_done = false;
    if (!attr_done) {
        cudaFuncSetAttribute(k_attn, cudaFuncAttributeMaxDynamicSharedMemorySize, 131072);
        cudaFuncSetAttribute(k_qgemm_mma, cudaFuncAttributeMaxDynamicSharedMemorySize, QSMEM);
        attr_done = true;
    }

    k_stats<<<4096, 256>>>(z, Wsr, Wsi);               /* idx 0 */
    k_build_bt<<<dim3(16, 16), 256>>>(Wrqr, Wrqi);     /* idx 1 */
    k_salience<<<128, 256>>>(out, sb, ns);             /* idx 2 */
    k_qgemm_mma<<<dim3(NC / BN, NT / BM), 256, QSMEM>>>();  /* idx 3: ncu */
    k_runs<<<Bb, 256>>>(out);
    k_evec<<<Bb * SS, 256>>>(z, out);
    k_eventkv<<<dim3(Bb, SS / 2), 512>>>(Wekr, Weki, Wevr, Wevi, sk, sv, out);
    k_udot<<<dim3(Bb, SS / 8, 2), 256>>>(out);
    k_mask<<<1, 256>>>(sm, out);
    k_attn<<<NT / 16, 512, 131072>>>(z, out, gain);
}

// round 9
// speedup vs baseline: 2.7438x; 1.2202x over previous
#include <cuda_runtime.h>
#include <cuda_fp16.h>
#include <math.h>
#include <stdint.h>

#define Bb   8
#define LL   4096
#define DIMC 512
#define SS   32
#define KK   8
#define NT   (Bb*LL)      /* 32768 tokens */
#define NC   (DIMC*2)     /* 1024 floats per token (interleaved r,i) */
#define THRv 0.5f
#define EPSv 1e-8f

/* output layout: concat(out, new_keys, new_values, new_mask, salience) */
#define OFF_OUT ((size_t)0)
#define OFF_NK  ((size_t)NT*NC)
#define OFF_NV  (OFF_NK + (size_t)Bb*SS*NC)
#define OFF_NM  (OFF_NV + (size_t)Bb*SS*NC)
#define OFF_SAL (OFF_NM + (size_t)Bb*SS)

/* scratch (device globals; no allocation allowed) */
__device__ float g_avg[NT];
__device__ float g_phase[NT];
__device__ float g_evec[Bb*SS*NC];
__device__ float g_emask[Bb*SS];
__device__ int   g_rs[Bb*SS];
__device__ int   g_re[Bb*SS];
__device__ float g_kmag[Bb*SS];
__device__ __half g_BhiT[NC*NC];          /* B^T fp16, [n][k], 2MB */
__device__ __half g_Ahi[(size_t)NT*NC];   /* z hi fp16, 64MB */
__device__ __half g_Alo[(size_t)NT*NC];   /* z lo fp16, 64MB */
__device__ float g_WrT[DIMC*DIMC];        /* W_rq_r transposed, 1MB */
__device__ float g_WiT[DIMC*DIMC];        /* W_rq_i transposed, 1MB */
__device__ __half g_uh[Bb*SS*NC];         /* u hi fp16 */
__device__ __half g_ul[Bb*SS*NC];         /* u lo fp16 */
__device__ float g_qp[(size_t)NT*4];      /* qmag^2 partials per N-block */
__device__ float g_dot[(size_t)NT*SS];    /* dot[l,s], 4MB */

__device__ __forceinline__ float wred(float v) {
    #pragma unroll
    for (int o = 16; o; o >>= 1) v += __shfl_xor_sync(0xffffffffu, v, o);
    return v;
}

__device__ __forceinline__ float fsqrt(float x) {
    float y; asm("sqrt.approx.f32 %0, %1;" : "=f"(y) : "f"(x)); return y;
}
__device__ __forceinline__ float frcp(float x) {
    float y; asm("rcp.approx.f32 %0, %1;" : "=f"(y) : "f"(x)); return y;
}
__device__ __forceinline__ float frsqrt(float x) {
    float y; asm("rsqrt.approx.f32 %0, %1;" : "=f"(y) : "f"(x)); return y;
}

__device__ __forceinline__ void hsplit(float x, __half& h, __half& l) {
    h = __float2half_rn(x);
    l = __float2half_rn(x - __half2float(h));
}

__device__ __forceinline__ uint32_t smem_u32(const void* p) {
    uint32_t a;
    asm("{ .reg .u64 t; cvta.to.shared.u64 t, %1; cvt.u32.u64 %0, t; }"
        : "=r"(a) : "l"(p));
    return a;
}

__device__ __forceinline__ void ldsm4(uint32_t* r, uint32_t addr) {
    asm volatile("ldmatrix.sync.aligned.m8n8.x4.shared.b16 {%0,%1,%2,%3}, [%4];"
        : "=r"(r[0]), "=r"(r[1]), "=r"(r[2]), "=r"(r[3]) : "r"(addr));
}

__device__ __forceinline__ void mma16816(float* d, const uint32_t* a,
                                         uint32_t b0, uint32_t b1) {
    asm volatile(
        "mma.sync.aligned.m16n8k16.row.col.f32.f16.f16.f32 "
        "{%0,%1,%2,%3}, {%4,%5,%6,%7}, {%8,%9}, {%0,%1,%2,%3};"
        : "+f"(d[0]), "+f"(d[1]), "+f"(d[2]), "+f"(d[3])
        : "r"(a[0]), "r"(a[1]), "r"(a[2]), "r"(a[3]), "r"(b0), "r"(b1));
}

#define CP16(dst, src) \
    asm volatile("cp.async.cg.shared.global [%0], [%1], 16;" \
                 :: "r"(dst), "l"(src) : "memory")
#define CP_COMMIT() asm volatile("cp.async.commit_group;" ::: "memory")
#define CP_WAIT1()  asm volatile("cp.async.wait_group 1;" ::: "memory")

/* ------------------------------------------------------------------ */
/* fused: per-token stats + z -> fp16 hi/lo split */
__global__ void k_stats(const float* __restrict__ z,
                        const float* __restrict__ Wsr,
                        const float* __restrict__ Wsi) {
    int gw = (blockIdx.x * blockDim.x + threadIdx.x) >> 5;
    int lane = threadIdx.x & 31;
    if (gw >= NT) return;
    const float4* z4 = (const float4*)(z + (size_t)gw * NC);
    __half2* ah = (__half2*)(g_Ahi + (size_t)gw * NC);
    __half2* al = (__half2*)(g_Alo + (size_t)gw * NC);
    float ms = 0.f, pr = 0.f, pi = 0.f;
    #pragma unroll
    for (int i = 0; i < 8; i++) {
        int p = lane + 32 * i;
        float4 v = z4[p];
        __half h0, l0, h1, l1, h2, l2, h3, l3;
        hsplit(v.x, h0, l0); hsplit(v.y, h1, l1);
        hsplit(v.z, h2, l2); hsplit(v.w, h3, l3);
        ah[2 * p]     = __halves2half2(h0, h1);
        ah[2 * p + 1] = __halves2half2(h2, h3);
        al[2 * p]     = __halves2half2(l0, l1);
        al[2 * p + 1] = __halves2half2(l2, l3);
        int d = 2 * p;
        ms += fsqrt(v.x*v.x + v.y*v.y + EPSv) + fsqrt(v.z*v.z + v.w*v.w + EPSv);
        float wr0 = Wsr[d], wi0 = Wsi[d], wr1 = Wsr[d+1], wi1 = Wsi[d+1];
        pr += v.x*wr0 - v.y*wi0 + v.z*wr1 - v.w*wi1;
        pi += v.x*wi0 + v.y*wr0 + v.z*wi1 + v.w*wr1;
    }
    ms = wred(ms); pr = wred(pr); pi = wred(pi);
    if (lane == 0) {
        g_avg[gw]   = ms * (1.f / DIMC);
        g_phase[gw] = fsqrt(pr*pr + pi*pi + EPSv);
    }
}

/* ------------------------------------------------------------------ */
__global__ void k_build_bt(const float* __restrict__ Wr,
                           const float* __restrict__ Wi) {
    __shared__ float tr[32][33], ti[32][33];
    int tx = threadIdx.x & 31, ty = threadIdx.x >> 5;
    int d0 = blockIdx.x * 32, e0 = blockIdx.y * 32;
    #pragma unroll
    for (int j = 0; j < 4; j++) {
        int d = d0 + ty + 8 * j;
        tr[ty + 8 * j][tx] = Wr[(size_t)d * DIMC + e0 + tx];
        ti[ty + 8 * j][tx] = Wi[(size_t)d * DIMC + e0 + tx];
    }
    __syncthreads();
    #pragma unroll
    for (int j = 0; j < 4; j++) {
        int e = e0 + ty + 8 * j;
        int d = d0 + tx;
        float wr = tr[tx][ty + 8 * j], wi = ti[tx][ty + 8 * j];
        size_t r0 = (size_t)(2 * e) * NC, r1 = (size_t)(2 * e + 1) * NC;
        g_BhiT[r0 + 2*d]     = __float2half_rn(wr);
        g_BhiT[r0 + 2*d + 1] = __float2half_rn(-wi);
        g_BhiT[r1 + 2*d]     = __float2half_rn(wi);
        g_BhiT[r1 + 2*d + 1] = __float2half_rn(wr);
        g_WrT[(size_t)e * DIMC + d] = wr;
        g_WiT[(size_t)e * DIMC + d] = wi;
    }
}

/* ------------------------------------------------------------------ */
__global__ void k_salience(float* __restrict__ out,
                           const float* __restrict__ sb,
                           const float* __restrict__ ns) {
    int i = blockIdx.x * blockDim.x + threadIdx.x;
    if (i >= NT) return;
    int l = i & (LL - 1);
    float lm = 0.f;
    #pragma unroll
    for (int o = -2; o <= 2; o++) {
        int ll = l + o;
        if (ll >= 0 && ll < LL) lm += g_avg[i + o];
    }
    lm *= 0.2f;
    float x = g_phase[i] + (g_avg[i] - lm) * ns[0] + sb[0];
    out[OFF_SAL + i] = frcp(1.f + __expf(-x));
}

/* per-batch run detection */
__global__ void k_runs(const float* __restrict__ out) {
    int b = blockIdx.x, tid = threadIdx.x;
    const float* s = out + OFF_SAL + (size_t)b * LL;
    __shared__ int scnt[256];
    int l0 = tid * 16;
    bool prev0 = (l0 > 0) && (s[l0 - 1] > THRv);
    bool pa = prev0;
    int cnt = 0;
    for (int j = 0; j < 16; j++) {
        bool ab = s[l0 + j] > THRv;
        cnt += (ab && !pa);
        pa = ab;
    }
    scnt[tid] = cnt;
    if (tid < SS) { g_rs[b*SS+tid] = 0; g_re[b*SS+tid] = 0; g_emask[b*SS+tid] = 0.f; }
    __syncthreads();
    if (tid == 0) {
        int a = 0;
        for (int t = 0; t < 256; t++) { int c = scnt[t]; scnt[t] = a; a += c; }
    }
    __syncthreads();
    int e = scnt[tid];
    pa = prev0;
    for (int j = 0; j < 16; j++) {
        int l = l0 + j;
        bool ab = s[l] > THRv;
        if (ab && !pa) {
            if (e < SS) { g_rs[b*SS + e] = l; g_emask[b*SS + e] = 1.f; }
            e++;
        }
        if (ab && (e - 1) < SS) {
            bool nx = (l + 1 < LL) && (s[l + 1] > THRv);
            if (!nx) g_re[b*SS + (e - 1)] = l + 1;
        }
        pa = ab;
    }
}

/* event vectors: weighted mean of z over each run */
__global__ void k_evec(const float* __restrict__ z,
                       const float* __restrict__ out) {
    int bs = blockIdx.x, b = bs / SS;
    int rs = g_rs[bs], re = g_re[bs];
    const float* sal = out + OFF_SAL + (size_t)b * LL;
    int t = threadIdx.x;
    float a0 = 0.f, a1 = 0.f, a2 = 0.f, a3 = 0.f, den = 0.f;
    for (int l = rs; l < re; l++) {
        float w = sal[l];
        den += w;
        const float* zt = z + ((size_t)b * LL + l) * NC;
        a0 += w * zt[t];       a1 += w * zt[t + 256];
        a2 += w * zt[t + 512]; a3 += w * zt[t + 768];
    }
    float inv = frcp(fmaxf(den, EPSv));
    float* ev = g_evec + (size_t)bs * NC;
    ev[t] = a0 * inv; ev[t + 256] = a1 * inv;
    ev[t + 512] = a2 * inv; ev[t + 768] = a3 * inv;
}

/* event K/V projection + blend + kmag + new_mask (fused) */
__global__ void k_eventkv(const float* __restrict__ Wekr, const float* __restrict__ Weki,
                          const float* __restrict__ Wevr, const float* __restrict__ Wevi,
                          const float* __restrict__ sk,   const float* __restrict__ svv,
                          const float* __restrict__ smk,  float* __restrict__ out) {
    int b = blockIdx.x, sg = blockIdx.y;
    int e = threadIdx.x;
    __shared__ float sv[2][NC];
    __shared__ float wpart[2][16];
    for (int i = threadIdx.x; i < 2 * NC; i += 512)
        ((float*)sv)[i] = g_evec[(size_t)(b * SS + sg * 2) * NC + i];
    __syncthreads();
    float KR[2] = {0.f, 0.f}, KI[2] = {0.f, 0.f};
    float VR[2] = {0.f, 0.f}, VI[2] = {0.f, 0.f};
    for (int d = 0; d < DIMC; d++) {
        float wkr = Wekr[d * DIMC + e], wki = Weki[d * DIMC + e];
        float wvr = Wevr[d * DIMC + e], wvi = Wevi[d * DIMC + e];
        #pragma unroll
        for (int s2 = 0; s2 < 2; s2++) {
            float zr = sv[s2][2 * d], zi = sv[s2][2 * d + 1];
            KR[s2] += zr * wkr - zi * wki;
            KI[s2] += zr * wki + zi * wkr;
            VR[s2] += zr * wvr - zi * wvi;
            VI[s2] += zr * wvi + zi * wvr;
        }
    }
    int lane = e & 31, wid = e >> 5;
    #pragma unroll
    for (int s2 = 0; s2 < 2; s2++) {
        int bs = b * SS + sg * 2 + s2;
        float m = g_emask[bs];
        size_t off = (size_t)bs * NC + 2 * e;
        float nkr = m * KR[s2] + (1.f - m) * sk[off];
        float nki = m * KI[s2] + (1.f - m) * sk[off + 1];
        float nvr = m * VR[s2] + (1.f - m) * svv[off];
        float nvi = m * VI[s2] + (1.f - m) * svv[off + 1];
        out[OFF_NK + off] = nkr; out[OFF_NK + off + 1] = nki;
        out[OFF_NV + off] = nvr; out[OFF_NV + off + 1] = nvi;
        if (e == 0) out[OFF_NM + bs] = fminf(smk[bs] + m, 1.f);
        float p = wred(nkr * nkr + nki * nki);
        if (lane == 0) wpart[s2][wid] = p;
    }
    __syncthreads();
    if (threadIdx.x < 2) {
        float sum = 0.f;
        for (int i = 0; i < 16; i++) sum += wpart[threadIdx.x][i];
        g_kmag[b * SS + sg * 2 + threadIdx.x] = fsqrt(sum + EPSv);
    }
}

/* ------------------------------------------------------------------ */
/* u_{b,s} = B * kappa_{b,s}, output split fp16 hi/lo */
__global__ void k_udot(const float* __restrict__ out) {
    __shared__ float ka[8][NC];
    int b = blockIdx.x, sg = blockIdx.y, eh = blockIdx.z;
    int tid = threadIdx.x;
    const float* ksrc = out + OFF_NK + (size_t)(b * SS + sg * 8) * NC;
    for (int i = tid; i < 8 * NC; i += 256)
        ((float*)ka)[i] = ksrc[i];
    __syncthreads();
    int e = eh * 256 + tid;
    float ur[8], ui[8];
    #pragma unroll
    for (int s = 0; s < 8; s++) { ur[s] = 0.f; ui[s] = 0.f; }
    for (int j = 0; j < DIMC; j++) {
        float wr = g_WrT[(size_t)j * DIMC + e];
        float wi = g_WiT[(size_t)j * DIMC + e];
        #pragma unroll
        for (int s = 0; s < 8; s++) {
            float2 kp = *(const float2*)&ka[s][2 * j];
            ur[s] += wr * kp.x + wi * kp.y;
            ui[s] += wr * kp.y - wi * kp.x;
        }
    }
    #pragma unroll
    for (int s = 0; s < 8; s++) {
        int bs = b * SS + sg * 8 + s;
        __half hr, lr, hi2, li;
        hsplit(ur[s], hr, lr);
        hsplit(ui[s], hi2, li);
        ((__half2*)(g_uh + (size_t)bs * NC))[e] = __halves2half2(hr, hi2);
        ((__half2*)(g_ul + (size_t)bs * NC))[e] = __halves2half2(lr, li);
    }
}

/* ------------------------------------------------------------------ */
/* qmag GEMM: single-term fp16, BM=128 BN=256 BK=32, 512 thr, 3-stage. */
#define BM 128
#define BN 256
#define PITCH 80
#define A_SZ (BM * PITCH)             /* 10240 */
#define B_SZ (BN * PITCH)             /* 20480 */
#define STAGE_SZ (A_SZ + B_SZ)        /* 30720 */
#define QSMEM (3 * STAGE_SZ)          /* 92160 */
#define NIT (NC / 32)                 /* 32 */

__global__ void __launch_bounds__(512, 1)
k_qgemm_mma() {
    extern __shared__ unsigned char smq[];
    __shared__ float qp_sm[4][BM];
    int t = threadIdx.x, lane = t & 31, wid = t >> 5;
    int m0 = blockIdx.y * BM, n0 = blockIdx.x * BN;
    int warpM = (wid & 3) * 32, warpN = (wid >> 2) * 64;

    uint32_t sb0 = smem_u32(smq);
    /* A: 1 cp16/thread/stage; B: 2 cp16/thread/stage */
    const uint4* srcA = (const uint4*)(g_Ahi  + (size_t)(m0 + (t >> 2)) * NC) + (t & 3);
    int bi0 = t, bi1 = t + 512;
    const uint4* srcB0 = (const uint4*)(g_BhiT + (size_t)(n0 + (bi0 >> 2)) * NC) + (bi0 & 3);
    const uint4* srcB1 = (const uint4*)(g_BhiT + (size_t)(n0 + (bi1 >> 2)) * NC) + (bi1 & 3);
    uint32_t dstA  = sb0 + (uint32_t)((t >> 2) * PITCH + (t & 3) * 16);
    uint32_t dstB0 = sb0 + (uint32_t)(A_SZ + (bi0 >> 2) * PITCH + (bi0 & 3) * 16);
    uint32_t dstB1 = sb0 + (uint32_t)(A_SZ + (bi1 >> 2) * PITCH + (bi1 & 3) * 16);

    uint32_t aoff = (uint32_t)((warpM + (lane & 15)) * PITCH + ((lane >> 4) << 4));
    uint32_t boff = (uint32_t)(A_SZ + (warpN + (lane & 7) + ((lane >> 4) & 1) * 8) * PITCH
                               + (((lane >> 3) & 1) << 4));

    float acc[2][8][4];
    #pragma unroll
    for (int i = 0; i < 2; i++)
        #pragma unroll
        for (int j = 0; j < 8; j++)
            #pragma unroll
            for (int k = 0; k < 4; k++) acc[i][j][k] = 0.f;

    #pragma unroll
    for (int s = 0; s < 2; s++) {
        uint32_t off = (uint32_t)(s * STAGE_SZ);
        CP16(dstA + off,  srcA  + s * 4);
        CP16(dstB0 + off, srcB0 + s * 4);
        CP16(dstB1 + off, srcB1 + s * 4);
        CP_COMMIT();
    }

    for (int it = 0; it < NIT; it++) {
        CP_WAIT1();
        __syncthreads();
        uint32_t st = sb0 + (uint32_t)((it % 3) * STAGE_SZ);
        uint32_t aAh = st + (aoff - 0);
        uint32_t aBh = st + boff;

        #pragma unroll
        for (int ko = 0; ko < 2; ko++) {
            uint32_t ah[2][4], bh[4][4];
            #pragma unroll
            for (int mg = 0; mg < 2; mg++)
                ldsm4(ah[mg], aAh + mg * (16 * PITCH) + ko * 32);
            #pragma unroll
            for (int ng = 0; ng < 4; ng++)
                ldsm4(bh[ng], aBh + ng * (16 * PITCH) + ko * 32);
            #pragma unroll
            for (int mg = 0; mg < 2; mg++)
                #pragma unroll
                for (int ng = 0; ng < 4; ng++)
                    #pragma unroll
                    for (int h = 0; h < 2; h++)
                        mma16816(acc[mg][ng * 2 + h], ah[mg],
                                 bh[ng][h*2], bh[ng][h*2+1]);
        }

        if (it + 2 < NIT) {
            uint32_t off = (uint32_t)(((it + 2) % 3) * STAGE_SZ);
            CP16(dstA + off,  srcA  + (it + 2) * 4);
            CP16(dstB0 + off, srcB0 + (it + 2) * 4);
            CP16(dstB1 + off, srcB1 + (it + 2) * 4);
        }
        CP_COMMIT();
    }

    #pragma unroll
    for (int mg = 0; mg < 2; mg++) {
        float rp0 = 0.f, rp1 = 0.f;
        #pragma unroll
        for (int j = 0; j < 8; j++) {
            float* d = acc[mg][j];
            rp0 += d[0]*d[0] + d[1]*d[1];
            rp1 += d[2]*d[2] + d[3]*d[3];
        }
        rp0 += __shfl_xor_sync(0xffffffffu, rp0, 1);
        rp0 += __shfl_xor_sync(0xffffffffu, rp0, 2);
        rp1 += __shfl_xor_sync(0xffffffffu, rp1, 1);
        rp1 += __shfl_xor_sync(0xffffffffu, rp1, 2);
        if ((lane & 3) == 0) {
            int r = warpM + mg * 16 + (lane >> 2);
            /* accumulate across the 4 n-warp groups via separate banks */
            qp_sm[wid >> 2][r]     = (wid >> 2) == 0 ? rp0 : rp0;
            qp_sm[wid >> 2][r + 8] = rp1;
        }
    }
    __syncthreads();
    if (t < BM)
        g_qp[(size_t)(m0 + t) * 4 + blockIdx.x] =
            qp_sm[0][t] + qp_sm[1][t] + qp_sm[2][t] + qp_sm[3][t];
}

/* ------------------------------------------------------------------ */
/* dot GEMM: dot[l,s] = z_l . u_s, 3-term fp16 (hh+hl+lh).
   BM=128 tokens/block, B (u hi+lo, 32x1024 fp16) fully smem-resident,
   A 3-stage cp.async. 256 blocks, 256 thr, 8 warps (warp = 16 rows). */
#define DM 128
#define DA_SZ (DM * PITCH)            /* 10240 per comp */
#define DSTG (2 * DA_SZ)              /* 20480 per stage */
#define PB 2064                       /* B row pitch bytes */
#define B_HL (SS * PB)                /* 66048 per comp */
#define DB_OFF (3 * DSTG)             /* 61440 */
#define DSMEM (DB_OFF + 2 * B_HL)     /* 193536 */
#define NITD (NC / 32)                /* 32 */

__global__ void __launch_bounds__(256, 1)
k_dotgemm() {
    extern __shared__ unsigned char smd[];
    int t = threadIdx.x, lane = t & 31, wid = t >> 5;
    int m0 = blockIdx.x * DM;
    int batch = blockIdx.x >> 5;              /* 4096/128 = 32 blocks/batch */
    int warpM = wid * 16;

    uint32_t sb0 = smem_u32(smd);

    /* load B (u hi/lo) resident: 32 rows x 128 uint4 per comp */
    #pragma unroll
    for (int u = 0; u < 16; u++) {
        int idx = t + 256 * u;
        int row = idx >> 7, col = idx & 127;
        uint32_t d0 = sb0 + (uint32_t)(DB_OFF + row * PB + col * 16);
        const uint4* sh = (const uint4*)(g_uh + (size_t)(batch * SS + row) * NC) + col;
        const uint4* sl = (const uint4*)(g_ul + (size_t)(batch * SS + row) * NC) + col;
        CP16(d0, sh);
        CP16(d0 + B_HL, sl);
    }
    /* A per stage: 2 cp16/thread/comp */
    int ai0 = t, ai1 = t + 256;
    const uint4* sAh0 = (const uint4*)(g_Ahi + (size_t)(m0 + (ai0 >> 2)) * NC) + (ai0 & 3);
    const uint4* sAh1 = (const uint4*)(g_Ahi + (size_t)(m0 + (ai1 >> 2)) * NC) + (ai1 & 3);
    const uint4* sAl0 = (const uint4*)(g_Alo + (size_t)(m0 + (ai0 >> 2)) * NC) + (ai0 & 3);
    const uint4* sAl1 = (const uint4*)(g_Alo + (size_t)(m0 + (ai1 >> 2)) * NC) + (ai1 & 3);
    uint32_t dA0 = sb0 + (uint32_t)((ai0 >> 2) * PITCH + (ai0 & 3) * 16);
    uint32_t dA1 = sb0 + (uint32_t)((ai1 >> 2) * PITCH + (ai1 & 3) * 16);

    /* stage 0 (grouped with B), stage 1 */
    #pragma unroll
    for (int s = 0; s < 2; s++) {
        uint32_t off = (uint32_t)(s * DSTG);
        CP16(dA0 + off, sAh0 + s * 4);          CP16(dA1 + off, sAh1 + s * 4);
        CP16(dA0 + off + DA_SZ, sAl0 + s * 4);  CP16(dA1 + off + DA_SZ, sAl1 + s * 4);
        CP_COMMIT();
    }

    uint32_t aoff = (uint32_t)((warpM + (lane & 15)) * PITCH + ((lane >> 4) << 4));
    uint32_t boffB = (uint32_t)(DB_OFF + ((lane & 7) + ((lane >> 4) & 1) * 8) * PB
                                + (((lane >> 3) & 1) << 4));

    float acc[4][4];
    #pragma unroll
    for (int j = 0; j < 4; j++)
        #pragma unroll
        for (int k = 0; k < 4; k++) acc[j][k] = 0.f;

    for (int it = 0; it < NITD; it++) {
        CP_WAIT1();
        __syncthreads();
        uint32_t st = sb0 + (uint32_t)((it % 3) * DSTG);
        #pragma unroll
        for (int ko = 0; ko < 2; ko++) {
            uint32_t ah[4], al[4], bh[2][4], bl[2][4];
            ldsm4(ah, st + aoff + ko * 32);
            ldsm4(al, st + DA_SZ + aoff + ko * 32);
            #pragma unroll
            for (int ng = 0; ng < 2; ng++) {
                uint32_t ba = sb0 + boffB + ng * (16 * PB) + it * 64 + ko * 32;
                ldsm4(bh[ng], ba);
                ldsm4(bl[ng], ba + B_HL);
            }
            #pragma unroll
            for (int ng = 0; ng < 2; ng++)
                #pragma unroll
                for (int h = 0; h < 2; h++) {
                    float* d = acc[ng * 2 + h];
                    mma16816(d, al, bh[ng][h*2], bh[ng][h*2+1]);
                    mma16816(d, ah, bl[ng][h*2], bl[ng][h*2+1]);
                    mma16816(d, ah, bh[ng][h*2], bh[ng][h*2+1]);
                }
        }
        if (it + 2 < NITD) {
            uint32_t off = (uint32_t)(((it + 2) % 3) * DSTG);
            CP16(dA0 + off, sAh0 + (it + 2) * 4);          CP16(dA1 + off, sAh1 + (it + 2) * 4);
            CP16(dA0 + off + DA_SZ, sAl0 + (it + 2) * 4);  CP16(dA1 + off + DA_SZ, sAl1 + (it + 2) * 4);
        }
        CP_COMMIT();
    }

    /* store dot: row r = m0+warpM+(lane>>2)(+8), col = j*8 + (lane&3)*2 */
    #pragma unroll
    for (int j = 0; j < 4; j++) {
        float* d = acc[j];
        int r = m0 + warpM + (lane >> 2);
        int c = j * 8 + (lane & 3) * 2;
        *(float2*)&g_dot[(size_t)r * SS + c]       = make_float2(d[0], d[1]);
        *(float2*)&g_dot[(size_t)(r + 8) * SS + c] = make_float2(d[2], d[3]);
    }
}

/* ------------------------------------------------------------------ */
/* attention: warp/token, 16 tokens/block; scores from g_dot, V staged. */
__global__ void k_attn(float* __restrict__ out, const float* __restrict__ gain) {
    extern __shared__ float4 sV[];             /* 32*256 float4 = 128KB */
    __shared__ float sKmag[SS];
    __shared__ float sMask[SS];
    int tid = threadIdx.x, warp = tid >> 5, lane = tid & 31;
    int tok0 = blockIdx.x * 16;
    int b = tok0 / LL;

    const float4* Vsrc = (const float4*)(out + OFF_NV + (size_t)b * SS * NC);
    for (int i = tid; i < SS * NC / 4; i += 512) sV[i] = Vsrc[i];
    if (tid < SS) {
        sKmag[tid] = g_kmag[b * SS + tid];
        sMask[tid] = out[OFF_NM + b * SS + tid];
    }
    __syncthreads();

    int token = tok0 + warp;
    float qp = (lane < 4) ? g_qp[(size_t)token * 4 + lane] : 0.f;
    qp = wred(qp);
    float qmag = fsqrt(qp + EPSv);

    float dval = g_dot[(size_t)token * SS + lane];
    float myscore = dval * frcp(qmag * sKmag[lane] + EPSv);
    if (sMask[lane] == 0.f) myscore = -1e9f;

    /* top-K with lowest-index tie break */
    float vcur = myscore;
    float topv[KK]; int topi[KK];
    #pragma unroll
    for (int j = 0; j < KK; j++) {
        float v = vcur; int idx = lane;
        #pragma unroll
        for (int o = 16; o; o >>= 1) {
            float v2 = __shfl_xor_sync(0xffffffffu, v, o);
            int   i2 = __shfl_xor_sync(0xffffffffu, idx, o);
            if (v2 > v || (v2 == v && i2 < idx)) { v = v2; idx = i2; }
        }
        topv[j] = v; topi[j] = idx;
        if (lane == idx) vcur = -INFINITY;
    }
    float w[KK], wsum = 0.f, mx = topv[0];
    #pragma unroll
    for (int j = 0; j < KK; j++) { w[j] = __expf(topv[j] - mx); wsum += w[j]; }
    float winv = frcp(wsum);

    float4 r[8];
    #pragma unroll
    for (int i = 0; i < 8; i++) r[i] = make_float4(0.f, 0.f, 0.f, 0.f);
    #pragma unroll
    for (int j = 0; j < KK; j++) {
        float a = w[j] * winv;
        const float4* Vr = sV + topi[j] * 256;
        #pragma unroll
        for (int i = 0; i < 8; i++) {
            float4 vv = Vr[lane + 32 * i];
            r[i].x += a * vv.x; r[i].y += a * vv.y;
            r[i].z += a * vv.z; r[i].w += a * vv.w;
        }
    }
    float ssum = 0.f;
    #pragma unroll
    for (int i = 0; i < 8; i++)
        ssum += r[i].x*r[i].x + r[i].y*r[i].y + r[i].z*r[i].z + r[i].w*r[i].w;
    ssum = wred(ssum);
    float rinv = frsqrt(ssum * (1.f / DIMC) + EPSv);

    const float2* g2 = (const float2*)gain;
    float4* orow = (float4*)(out + (size_t)token * NC);
    #pragma unroll
    for (int i = 0; i < 8; i++) {
        float2 g = g2[lane + 32 * i];
        float4 o;
        o.x = r[i].x * rinv * g.x; o.y = r[i].y * rinv * g.x;
        o.z = r[i].z * rinv * g.y; o.w = r[i].w * rinv * g.y;
        orow[lane + 32 * i] = o;
    }
}

/* ------------------------------------------------------------------ */
extern "C" void kernel_launch(void* const* d_in, const int* in_sizes, int n_in,
                              void* d_out, int out_size) {
    const float* z    = (const float*)d_in[0];
    const float* sk   = (const float*)d_in[1];
    const float* sv   = (const float*)d_in[2];
    const float* sm   = (const float*)d_in[3];
    const float* Wsr  = (const float*)d_in[4];
    const float* Wsi  = (const float*)d_in[5];
    const float* sb   = (const float*)d_in[6];
    const float* ns   = (const float*)d_in[7];
    const float* Wekr = (const float*)d_in[8];
    const float* Weki = (const float*)d_in[9];
    const float* Wevr = (const float*)d_in[10];
    const float* Wevi = (const float*)d_in[11];
    const float* Wrqr = (const float*)d_in[12];
    const float* Wrqi = (const float*)d_in[13];
    const float* gain = (const float*)d_in[14];
    float* out = (float*)d_out;

    static bool attr_done = false;
    if (!attr_done) {
        cudaFuncSetAttribute(k_attn, cudaFuncAttributeMaxDynamicSharedMemorySize, 131072);
        cudaFuncSetAttribute(k_qgemm_mma, cudaFuncAttributeMaxDynamicSharedMemorySize, QSMEM);
        cudaFuncSetAttribute(k_dotgemm, cudaFuncAttributeMaxDynamicSharedMemorySize, DSMEM);
        attr_done = true;
    }

    k_stats<<<4096, 256>>>(z, Wsr, Wsi);                    /* idx 0 */
    k_build_bt<<<dim3(16, 16), 256>>>(Wrqr, Wrqi);          /* idx 1 */
    k_salience<<<128, 256>>>(out, sb, ns);                  /* idx 2 */
    k_qgemm_mma<<<dim3(NC / BN, NT / BM), 512, QSMEM>>>();  /* idx 3: profiled */
    k_runs<<<Bb, 256>>>(out);
    k_evec<<<Bb * SS, 256>>>(z, out);
    k_eventkv<<<dim3(Bb, SS / 2), 512>>>(Wekr, Weki, Wevr, Wevi, sk, sv, sm, out);
    k_udot<<<dim3(Bb, SS / 8, 2), 256>>>(out);
    k_dotgemm<<<NT / DM, 256, DSMEM>>>();
    k_attn<<<NT / 16, 512, 131072>>>(out, gain);
}

// round 10
// speedup vs baseline: 2.9629x; 1.0798x over previous
#include <cuda_runtime.h>
#include <cuda_fp16.h>
#include <math.h>
#include <stdint.h>

#define Bb   8
#define LL   4096
#define DIMC 512
#define SS   32
#define KK   8
#define NT   (Bb*LL)      /* 32768 tokens */
#define NC   (DIMC*2)     /* 1024 floats per token (interleaved r,i) */
#define THRv 0.5f
#define EPSv 1e-8f

/* output layout: concat(out, new_keys, new_values, new_mask, salience) */
#define OFF_OUT ((size_t)0)
#define OFF_NK  ((size_t)NT*NC)
#define OFF_NV  (OFF_NK + (size_t)Bb*SS*NC)
#define OFF_NM  (OFF_NV + (size_t)Bb*SS*NC)
#define OFF_SAL (OFF_NM + (size_t)Bb*SS)

/* scratch (device globals; no allocation allowed) */
__device__ float g_avg[NT];
__device__ float g_phase[NT];
__device__ float g_evec[Bb*SS*NC];
__device__ float g_emask[Bb*SS];
__device__ int   g_rs[Bb*SS];
__device__ int   g_re[Bb*SS];
__device__ float g_kmag[Bb*SS];
__device__ __half g_BhiT[NC*NC];          /* B^T fp16, [n][k], 2MB */
__device__ __half g_Ahi[(size_t)NT*NC];   /* z hi fp16, 64MB */
__device__ __half g_Alo[(size_t)NT*NC];   /* z lo fp16, 64MB */
__device__ float g_WrT[DIMC*DIMC];        /* W_rq_r transposed, 1MB */
__device__ float g_WiT[DIMC*DIMC];        /* W_rq_i transposed, 1MB */
__device__ __half g_uh[Bb*SS*NC];         /* u hi fp16 */
__device__ __half g_ul[Bb*SS*NC];         /* u lo fp16 */
__device__ float g_qp[(size_t)NT*4];      /* qmag^2 partials per N-block */
__device__ float g_dot[(size_t)NT*SS];    /* dot[l,s], 4MB */

__device__ __forceinline__ float wred(float v) {
    #pragma unroll
    for (int o = 16; o; o >>= 1) v += __shfl_xor_sync(0xffffffffu, v, o);
    return v;
}

__device__ __forceinline__ float fsqrt(float x) {
    float y; asm("sqrt.approx.f32 %0, %1;" : "=f"(y) : "f"(x)); return y;
}
__device__ __forceinline__ float frcp(float x) {
    float y; asm("rcp.approx.f32 %0, %1;" : "=f"(y) : "f"(x)); return y;
}
__device__ __forceinline__ float frsqrt(float x) {
    float y; asm("rsqrt.approx.f32 %0, %1;" : "=f"(y) : "f"(x)); return y;
}

__device__ __forceinline__ void hsplit(float x, __half& h, __half& l) {
    h = __float2half_rn(x);
    l = __float2half_rn(x - __half2float(h));
}

__device__ __forceinline__ uint32_t smem_u32(const void* p) {
    uint32_t a;
    asm("{ .reg .u64 t; cvta.to.shared.u64 t, %1; cvt.u32.u64 %0, t; }"
        : "=r"(a) : "l"(p));
    return a;
}

__device__ __forceinline__ void ldsm4(uint32_t* r, uint32_t addr) {
    asm volatile("ldmatrix.sync.aligned.m8n8.x4.shared.b16 {%0,%1,%2,%3}, [%4];"
        : "=r"(r[0]), "=r"(r[1]), "=r"(r[2]), "=r"(r[3]) : "r"(addr));
}

__device__ __forceinline__ void mma16816(float* d, const uint32_t* a,
                                         uint32_t b0, uint32_t b1) {
    asm volatile(
        "mma.sync.aligned.m16n8k16.row.col.f32.f16.f16.f32 "
        "{%0,%1,%2,%3}, {%4,%5,%6,%7}, {%8,%9}, {%0,%1,%2,%3};"
        : "+f"(d[0]), "+f"(d[1]), "+f"(d[2]), "+f"(d[3])
        : "r"(a[0]), "r"(a[1]), "r"(a[2]), "r"(a[3]), "r"(b0), "r"(b1));
}

#define CP16(dst, src) \
    asm volatile("cp.async.cg.shared.global [%0], [%1], 16;" \
                 :: "r"(dst), "l"(src) : "memory")
#define CP_COMMIT() asm volatile("cp.async.commit_group;" ::: "memory")
#define CP_WAIT1()  asm volatile("cp.async.wait_group 1;" ::: "memory")

/* ------------------------------------------------------------------ */
/* fused: per-token stats + z -> fp16 hi/lo split */
__global__ void k_stats(const float* __restrict__ z,
                        const float* __restrict__ Wsr,
                        const float* __restrict__ Wsi) {
    int gw = (blockIdx.x * blockDim.x + threadIdx.x) >> 5;
    int lane = threadIdx.x & 31;
    if (gw >= NT) return;
    const float4* z4 = (const float4*)(z + (size_t)gw * NC);
    __half2* ah = (__half2*)(g_Ahi + (size_t)gw * NC);
    __half2* al = (__half2*)(g_Alo + (size_t)gw * NC);
    float ms = 0.f, pr = 0.f, pi = 0.f;
    #pragma unroll
    for (int i = 0; i < 8; i++) {
        int p = lane + 32 * i;
        float4 v = z4[p];
        __half h0, l0, h1, l1, h2, l2, h3, l3;
        hsplit(v.x, h0, l0); hsplit(v.y, h1, l1);
        hsplit(v.z, h2, l2); hsplit(v.w, h3, l3);
        ah[2 * p]     = __halves2half2(h0, h1);
        ah[2 * p + 1] = __halves2half2(h2, h3);
        al[2 * p]     = __halves2half2(l0, l1);
        al[2 * p + 1] = __halves2half2(l2, l3);
        int d = 2 * p;
        ms += fsqrt(v.x*v.x + v.y*v.y + EPSv) + fsqrt(v.z*v.z + v.w*v.w + EPSv);
        float wr0 = Wsr[d], wi0 = Wsi[d], wr1 = Wsr[d+1], wi1 = Wsi[d+1];
        pr += v.x*wr0 - v.y*wi0 + v.z*wr1 - v.w*wi1;
        pi += v.x*wi0 + v.y*wr0 + v.z*wi1 + v.w*wr1;
    }
    ms = wred(ms); pr = wred(pr); pi = wred(pi);
    if (lane == 0) {
        g_avg[gw]   = ms * (1.f / DIMC);
        g_phase[gw] = fsqrt(pr*pr + pi*pi + EPSv);
    }
}

/* ------------------------------------------------------------------ */
__global__ void k_build_bt(const float* __restrict__ Wr,
                           const float* __restrict__ Wi) {
    __shared__ float tr[32][33], ti[32][33];
    int tx = threadIdx.x & 31, ty = threadIdx.x >> 5;
    int d0 = blockIdx.x * 32, e0 = blockIdx.y * 32;
    #pragma unroll
    for (int j = 0; j < 4; j++) {
        int d = d0 + ty + 8 * j;
        tr[ty + 8 * j][tx] = Wr[(size_t)d * DIMC + e0 + tx];
        ti[ty + 8 * j][tx] = Wi[(size_t)d * DIMC + e0 + tx];
    }
    __syncthreads();
    #pragma unroll
    for (int j = 0; j < 4; j++) {
        int e = e0 + ty + 8 * j;
        int d = d0 + tx;
        float wr = tr[tx][ty + 8 * j], wi = ti[tx][ty + 8 * j];
        size_t r0 = (size_t)(2 * e) * NC, r1 = (size_t)(2 * e + 1) * NC;
        g_BhiT[r0 + 2*d]     = __float2half_rn(wr);
        g_BhiT[r0 + 2*d + 1] = __float2half_rn(-wi);
        g_BhiT[r1 + 2*d]     = __float2half_rn(wi);
        g_BhiT[r1 + 2*d + 1] = __float2half_rn(wr);
        g_WrT[(size_t)e * DIMC + d] = wr;
        g_WiT[(size_t)e * DIMC + d] = wi;
    }
}

/* ------------------------------------------------------------------ */
/* fused salience + run detection: one block per batch.
   salience computed into smem (and written to out), then scanned. */
__global__ void k_runs(float* __restrict__ out,
                       const float* __restrict__ sb,
                       const float* __restrict__ ns) {
    __shared__ float sal[LL];     /* 16KB */
    __shared__ int scnt[256];
    int b = blockIdx.x, tid = threadIdx.x;
    float nsv = ns[0], sbv = sb[0];

    int l0 = tid * 16;
    for (int j = 0; j < 16; j++) {
        int l = l0 + j;
        int i = b * LL + l;
        float lm = 0.f;
        #pragma unroll
        for (int o = -2; o <= 2; o++) {
            int ll = l + o;
            if (ll >= 0 && ll < LL) lm += g_avg[i + o];
        }
        lm *= 0.2f;
        float x = g_phase[i] + (g_avg[i] - lm) * nsv + sbv;
        float s = frcp(1.f + __expf(-x));
        sal[l] = s;
        out[OFF_SAL + i] = s;
    }
    if (tid < SS) { g_rs[b*SS+tid] = 0; g_re[b*SS+tid] = 0; g_emask[b*SS+tid] = 0.f; }
    __syncthreads();

    bool prev0 = (l0 > 0) && (sal[l0 - 1] > THRv);
    bool pa = prev0;
    int cnt = 0;
    for (int j = 0; j < 16; j++) {
        bool ab = sal[l0 + j] > THRv;
        cnt += (ab && !pa);
        pa = ab;
    }
    scnt[tid] = cnt;
    __syncthreads();
    if (tid == 0) {
        int a = 0;
        for (int t = 0; t < 256; t++) { int c = scnt[t]; scnt[t] = a; a += c; }
    }
    __syncthreads();
    int e = scnt[tid];
    pa = prev0;
    for (int j = 0; j < 16; j++) {
        int l = l0 + j;
        bool ab = sal[l] > THRv;
        if (ab && !pa) {
            if (e < SS) { g_rs[b*SS + e] = l; g_emask[b*SS + e] = 1.f; }
            e++;
        }
        if (ab && (e - 1) < SS) {
            bool nx = (l + 1 < LL) && (sal[l + 1] > THRv);
            if (!nx) g_re[b*SS + (e - 1)] = l + 1;
        }
        pa = ab;
    }
}

/* event vectors: weighted mean of z over each run */
__global__ void k_evec(const float* __restrict__ z,
                       const float* __restrict__ out) {
    int bs = blockIdx.x, b = bs / SS;
    int rs = g_rs[bs], re = g_re[bs];
    const float* sal = out + OFF_SAL + (size_t)b * LL;
    int t = threadIdx.x;
    float a0 = 0.f, a1 = 0.f, a2 = 0.f, a3 = 0.f, den = 0.f;
    for (int l = rs; l < re; l++) {
        float w = sal[l];
        den += w;
        const float* zt = z + ((size_t)b * LL + l) * NC;
        a0 += w * zt[t];       a1 += w * zt[t + 256];
        a2 += w * zt[t + 512]; a3 += w * zt[t + 768];
    }
    float inv = frcp(fmaxf(den, EPSv));
    float* ev = g_evec + (size_t)bs * NC;
    ev[t] = a0 * inv; ev[t + 256] = a1 * inv;
    ev[t + 512] = a2 * inv; ev[t + 768] = a3 * inv;
}

/* event K/V projection + blend + kmag + new_mask (fused) */
__global__ void k_eventkv(const float* __restrict__ Wekr, const float* __restrict__ Weki,
                          const float* __restrict__ Wevr, const float* __restrict__ Wevi,
                          const float* __restrict__ sk,   const float* __restrict__ svv,
                          const float* __restrict__ smk,  float* __restrict__ out) {
    int b = blockIdx.x, sg = blockIdx.y;
    int e = threadIdx.x;
    __shared__ float sv[2][NC];
    __shared__ float wpart[2][16];
    for (int i = threadIdx.x; i < 2 * NC; i += 512)
        ((float*)sv)[i] = g_evec[(size_t)(b * SS + sg * 2) * NC + i];
    __syncthreads();
    float KR[2] = {0.f, 0.f}, KI[2] = {0.f, 0.f};
    float VR[2] = {0.f, 0.f}, VI[2] = {0.f, 0.f};
    for (int d = 0; d < DIMC; d++) {
        float wkr = Wekr[d * DIMC + e], wki = Weki[d * DIMC + e];
        float wvr = Wevr[d * DIMC + e], wvi = Wevi[d * DIMC + e];
        #pragma unroll
        for (int s2 = 0; s2 < 2; s2++) {
            float zr = sv[s2][2 * d], zi = sv[s2][2 * d + 1];
            KR[s2] += zr * wkr - zi * wki;
            KI[s2] += zr * wki + zi * wkr;
            VR[s2] += zr * wvr - zi * wvi;
            VI[s2] += zr * wvi + zi * wvr;
        }
    }
    int lane = e & 31, wid = e >> 5;
    #pragma unroll
    for (int s2 = 0; s2 < 2; s2++) {
        int bs = b * SS + sg * 2 + s2;
        float m = g_emask[bs];
        size_t off = (size_t)bs * NC + 2 * e;
        float nkr = m * KR[s2] + (1.f - m) * sk[off];
        float nki = m * KI[s2] + (1.f - m) * sk[off + 1];
        float nvr = m * VR[s2] + (1.f - m) * svv[off];
        float nvi = m * VI[s2] + (1.f - m) * svv[off + 1];
        out[OFF_NK + off] = nkr; out[OFF_NK + off + 1] = nki;
        out[OFF_NV + off] = nvr; out[OFF_NV + off + 1] = nvi;
        if (e == 0) out[OFF_NM + bs] = fminf(smk[bs] + m, 1.f);
        float p = wred(nkr * nkr + nki * nki);
        if (lane == 0) wpart[s2][wid] = p;
    }
    __syncthreads();
    if (threadIdx.x < 2) {
        float sum = 0.f;
        for (int i = 0; i < 16; i++) sum += wpart[threadIdx.x][i];
        g_kmag[b * SS + sg * 2 + threadIdx.x] = fsqrt(sum + EPSv);
    }
}

/* ------------------------------------------------------------------ */
/* u_{b,s} = B * kappa_{b,s}, output split fp16 hi/lo */
__global__ void k_udot(const float* __restrict__ out) {
    __shared__ float ka[8][NC];
    int b = blockIdx.x, sg = blockIdx.y, eh = blockIdx.z;
    int tid = threadIdx.x;
    const float* ksrc = out + OFF_NK + (size_t)(b * SS + sg * 8) * NC;
    for (int i = tid; i < 8 * NC; i += 256)
        ((float*)ka)[i] = ksrc[i];
    __syncthreads();
    int e = eh * 256 + tid;
    float ur[8], ui[8];
    #pragma unroll
    for (int s = 0; s < 8; s++) { ur[s] = 0.f; ui[s] = 0.f; }
    for (int j = 0; j < DIMC; j++) {
        float wr = g_WrT[(size_t)j * DIMC + e];
        float wi = g_WiT[(size_t)j * DIMC + e];
        #pragma unroll
        for (int s = 0; s < 8; s++) {
            float2 kp = *(const float2*)&ka[s][2 * j];
            ur[s] += wr * kp.x + wi * kp.y;
            ui[s] += wr * kp.y - wi * kp.x;
        }
    }
    #pragma unroll
    for (int s = 0; s < 8; s++) {
        int bs = b * SS + sg * 8 + s;
        __half hr, lr, hi2, li;
        hsplit(ur[s], hr, lr);
        hsplit(ui[s], hi2, li);
        ((__half2*)(g_uh + (size_t)bs * NC))[e] = __halves2half2(hr, hi2);
        ((__half2*)(g_ul + (size_t)bs * NC))[e] = __halves2half2(lr, li);
    }
}

/* ------------------------------------------------------------------ */
/* qmag GEMM: single-term fp16, BM=128 BN=256 BK=32, 512 thr, 3-stage. */
#define BM 128
#define BN 256
#define PITCH 80
#define A_SZ (BM * PITCH)             /* 10240 */
#define B_SZ (BN * PITCH)             /* 20480 */
#define STAGE_SZ (A_SZ + B_SZ)        /* 30720 */
#define QSMEM (3 * STAGE_SZ)          /* 92160 */
#define NIT (NC / 32)                 /* 32 */

__global__ void __launch_bounds__(512, 1)
k_qgemm_mma() {
    extern __shared__ unsigned char smq[];
    __shared__ float qp_sm[4][BM];
    int t = threadIdx.x, lane = t & 31, wid = t >> 5;
    int m0 = blockIdx.y * BM, n0 = blockIdx.x * BN;
    int warpM = (wid & 3) * 32, warpN = (wid >> 2) * 64;

    uint32_t sb0 = smem_u32(smq);
    const uint4* srcA = (const uint4*)(g_Ahi  + (size_t)(m0 + (t >> 2)) * NC) + (t & 3);
    int bi0 = t, bi1 = t + 512;
    const uint4* srcB0 = (const uint4*)(g_BhiT + (size_t)(n0 + (bi0 >> 2)) * NC) + (bi0 & 3);
    const uint4* srcB1 = (const uint4*)(g_BhiT + (size_t)(n0 + (bi1 >> 2)) * NC) + (bi1 & 3);
    uint32_t dstA  = sb0 + (uint32_t)((t >> 2) * PITCH + (t & 3) * 16);
    uint32_t dstB0 = sb0 + (uint32_t)(A_SZ + (bi0 >> 2) * PITCH + (bi0 & 3) * 16);
    uint32_t dstB1 = sb0 + (uint32_t)(A_SZ + (bi1 >> 2) * PITCH + (bi1 & 3) * 16);

    uint32_t aoff = (uint32_t)((warpM + (lane & 15)) * PITCH + ((lane >> 4) << 4));
    uint32_t boff = (uint32_t)(A_SZ + (warpN + (lane & 7) + ((lane >> 4) & 1) * 8) * PITCH
                               + (((lane >> 3) & 1) << 4));

    float acc[2][8][4];
    #pragma unroll
    for (int i = 0; i < 2; i++)
        #pragma unroll
        for (int j = 0; j < 8; j++)
            #pragma unroll
            for (int k = 0; k < 4; k++) acc[i][j][k] = 0.f;

    #pragma unroll
    for (int s = 0; s < 2; s++) {
        uint32_t off = (uint32_t)(s * STAGE_SZ);
        CP16(dstA + off,  srcA  + s * 4);
        CP16(dstB0 + off, srcB0 + s * 4);
        CP16(dstB1 + off, srcB1 + s * 4);
        CP_COMMIT();
    }

    for (int it = 0; it < NIT; it++) {
        CP_WAIT1();
        __syncthreads();
        uint32_t st = sb0 + (uint32_t)((it % 3) * STAGE_SZ);
        uint32_t aAh = st + aoff;
        uint32_t aBh = st + boff;

        #pragma unroll
        for (int ko = 0; ko < 2; ko++) {
            uint32_t ah[2][4], bh[4][4];
            #pragma unroll
            for (int mg = 0; mg < 2; mg++)
                ldsm4(ah[mg], aAh + mg * (16 * PITCH) + ko * 32);
            #pragma unroll
            for (int ng = 0; ng < 4; ng++)
                ldsm4(bh[ng], aBh + ng * (16 * PITCH) + ko * 32);
            #pragma unroll
            for (int mg = 0; mg < 2; mg++)
                #pragma unroll
                for (int ng = 0; ng < 4; ng++)
                    #pragma unroll
                    for (int h = 0; h < 2; h++)
                        mma16816(acc[mg][ng * 2 + h], ah[mg],
                                 bh[ng][h*2], bh[ng][h*2+1]);
        }

        if (it + 2 < NIT) {
            uint32_t off = (uint32_t)(((it + 2) % 3) * STAGE_SZ);
            CP16(dstA + off,  srcA  + (it + 2) * 4);
            CP16(dstB0 + off, srcB0 + (it + 2) * 4);
            CP16(dstB1 + off, srcB1 + (it + 2) * 4);
        }
        CP_COMMIT();
    }

    #pragma unroll
    for (int mg = 0; mg < 2; mg++) {
        float rp0 = 0.f, rp1 = 0.f;
        #pragma unroll
        for (int j = 0; j < 8; j++) {
            float* d = acc[mg][j];
            rp0 += d[0]*d[0] + d[1]*d[1];
            rp1 += d[2]*d[2] + d[3]*d[3];
        }
        rp0 += __shfl_xor_sync(0xffffffffu, rp0, 1);
        rp0 += __shfl_xor_sync(0xffffffffu, rp0, 2);
        rp1 += __shfl_xor_sync(0xffffffffu, rp1, 1);
        rp1 += __shfl_xor_sync(0xffffffffu, rp1, 2);
        if ((lane & 3) == 0) {
            int r = warpM + mg * 16 + (lane >> 2);
            qp_sm[wid >> 2][r]     = rp0;
            qp_sm[wid >> 2][r + 8] = rp1;
        }
    }
    __syncthreads();
    if (t < BM)
        g_qp[(size_t)(m0 + t) * 4 + blockIdx.x] =
            qp_sm[0][t] + qp_sm[1][t] + qp_sm[2][t] + qp_sm[3][t];
}

/* ------------------------------------------------------------------ */
/* dot GEMM: dot[l,s] = z_l . u_s, 3-term fp16 (hh+hl+lh). */
#define DM 128
#define DA_SZ (DM * PITCH)            /* 10240 per comp */
#define DSTG (2 * DA_SZ)              /* 20480 per stage */
#define PB 2064                       /* B row pitch bytes */
#define B_HL (SS * PB)                /* 66048 per comp */
#define DB_OFF (3 * DSTG)             /* 61440 */
#define DSMEM (DB_OFF + 2 * B_HL)     /* 193536 */
#define NITD (NC / 32)                /* 32 */

__global__ void __launch_bounds__(256, 1)
k_dotgemm() {
    extern __shared__ unsigned char smd[];
    int t = threadIdx.x, lane = t & 31, wid = t >> 5;
    int m0 = blockIdx.x * DM;
    int batch = blockIdx.x >> 5;
    int warpM = wid * 16;

    uint32_t sb0 = smem_u32(smd);

    #pragma unroll
    for (int u = 0; u < 16; u++) {
        int idx = t + 256 * u;
        int row = idx >> 7, col = idx & 127;
        uint32_t d0 = sb0 + (uint32_t)(DB_OFF + row * PB + col * 16);
        const uint4* sh = (const uint4*)(g_uh + (size_t)(batch * SS + row) * NC) + col;
        const uint4* sl = (const uint4*)(g_ul + (size_t)(batch * SS + row) * NC) + col;
        CP16(d0, sh);
        CP16(d0 + B_HL, sl);
    }
    int ai0 = t, ai1 = t + 256;
    const uint4* sAh0 = (const uint4*)(g_Ahi + (size_t)(m0 + (ai0 >> 2)) * NC) + (ai0 & 3);
    const uint4* sAh1 = (const uint4*)(g_Ahi + (size_t)(m0 + (ai1 >> 2)) * NC) + (ai1 & 3);
    const uint4* sAl0 = (const uint4*)(g_Alo + (size_t)(m0 + (ai0 >> 2)) * NC) + (ai0 & 3);
    const uint4* sAl1 = (const uint4*)(g_Alo + (size_t)(m0 + (ai1 >> 2)) * NC) + (ai1 & 3);
    uint32_t dA0 = sb0 + (uint32_t)((ai0 >> 2) * PITCH + (ai0 & 3) * 16);
    uint32_t dA1 = sb0 + (uint32_t)((ai1 >> 2) * PITCH + (ai1 & 3) * 16);

    #pragma unroll
    for (int s = 0; s < 2; s++) {
        uint32_t off = (uint32_t)(s * DSTG);
        CP16(dA0 + off, sAh0 + s * 4);          CP16(dA1 + off, sAh1 + s * 4);
        CP16(dA0 + off + DA_SZ, sAl0 + s * 4);  CP16(dA1 + off + DA_SZ, sAl1 + s * 4);
        CP_COMMIT();
    }

    uint32_t aoff = (uint32_t)((warpM + (lane & 15)) * PITCH + ((lane >> 4) << 4));
    uint32_t boffB = (uint32_t)(DB_OFF + ((lane & 7) + ((lane >> 4) & 1) * 8) * PB
                                + (((lane >> 3) & 1) << 4));

    float acc[4][4];
    #pragma unroll
    for (int j = 0; j < 4; j++)
        #pragma unroll
        for (int k = 0; k < 4; k++) acc[j][k] = 0.f;

    for (int it = 0; it < NITD; it++) {
        CP_WAIT1();
        __syncthreads();
        uint32_t st = sb0 + (uint32_t)((it % 3) * DSTG);
        #pragma unroll
        for (int ko = 0; ko < 2; ko++) {
            uint32_t ah[4], al[4], bh[2][4], bl[2][4];
            ldsm4(ah, st + aoff + ko * 32);
            ldsm4(al, st + DA_SZ + aoff + ko * 32);
            #pragma unroll
            for (int ng = 0; ng < 2; ng++) {
                uint32_t ba = sb0 + boffB + ng * (16 * PB) + it * 64 + ko * 32;
                ldsm4(bh[ng], ba);
                ldsm4(bl[ng], ba + B_HL);
            }
            #pragma unroll
            for (int ng = 0; ng < 2; ng++)
                #pragma unroll
                for (int h = 0; h < 2; h++) {
                    float* d = acc[ng * 2 + h];
                    mma16816(d, al, bh[ng][h*2], bh[ng][h*2+1]);
                    mma16816(d, ah, bl[ng][h*2], bl[ng][h*2+1]);
                    mma16816(d, ah, bh[ng][h*2], bh[ng][h*2+1]);
                }
        }
        if (it + 2 < NITD) {
            uint32_t off = (uint32_t)(((it + 2) % 3) * DSTG);
            CP16(dA0 + off, sAh0 + (it + 2) * 4);          CP16(dA1 + off, sAh1 + (it + 2) * 4);
            CP16(dA0 + off + DA_SZ, sAl0 + (it + 2) * 4);  CP16(dA1 + off + DA_SZ, sAl1 + (it + 2) * 4);
        }
        CP_COMMIT();
    }

    #pragma unroll
    for (int j = 0; j < 4; j++) {
        float* d = acc[j];
        int r = m0 + warpM + (lane >> 2);
        int c = j * 8 + (lane & 3) * 2;
        *(float2*)&g_dot[(size_t)r * SS + c]       = make_float2(d[0], d[1]);
        *(float2*)&g_dot[(size_t)(r + 8) * SS + c] = make_float2(d[2], d[3]);
    }
}

/* ------------------------------------------------------------------ */
/* attention: warp/token, 32 tokens/block (1024 thr); V staged in smem. */
__global__ void __launch_bounds__(1024, 1)
k_attn(float* __restrict__ out, const float* __restrict__ gain) {
    extern __shared__ float4 sV[];             /* 32*256 float4 = 128KB */
    __shared__ float sKmag[SS];
    __shared__ float sMask[SS];
    int tid = threadIdx.x, warp = tid >> 5, lane = tid & 31;
    int tok0 = blockIdx.x * 32;
    int b = tok0 / LL;

    const float4* Vsrc = (const float4*)(out + OFF_NV + (size_t)b * SS * NC);
    for (int i = tid; i < SS * NC / 4; i += 1024) sV[i] = Vsrc[i];
    if (tid < SS) {
        sKmag[tid] = g_kmag[b * SS + tid];
        sMask[tid] = out[OFF_NM + b * SS + tid];
    }
    __syncthreads();

    int token = tok0 + warp;
    float qp = (lane < 4) ? g_qp[(size_t)token * 4 + lane] : 0.f;
    qp = wred(qp);
    float qmag = fsqrt(qp + EPSv);

    float dval = g_dot[(size_t)token * SS + lane];
    float myscore = dval * frcp(qmag * sKmag[lane] + EPSv);
    if (sMask[lane] == 0.f) myscore = -1e9f;

    /* top-K with lowest-index tie break */
    float vcur = myscore;
    float topv[KK]; int topi[KK];
    #pragma unroll
    for (int j = 0; j < KK; j++) {
        float v = vcur; int idx = lane;
        #pragma unroll
        for (int o = 16; o; o >>= 1) {
            float v2 = __shfl_xor_sync(0xffffffffu, v, o);
            int   i2 = __shfl_xor_sync(0xffffffffu, idx, o);
            if (v2 > v || (v2 == v && i2 < idx)) { v = v2; idx = i2; }
        }
        topv[j] = v; topi[j] = idx;
        if (lane == idx) vcur = -INFINITY;
    }
    float w[KK], wsum = 0.f, mx = topv[0];
    #pragma unroll
    for (int j = 0; j < KK; j++) { w[j] = __expf(topv[j] - mx); wsum += w[j]; }
    float winv = frcp(wsum);

    float4 r[8];
    #pragma unroll
    for (int i = 0; i < 8; i++) r[i] = make_float4(0.f, 0.f, 0.f, 0.f);
    #pragma unroll
    for (int j = 0; j < KK; j++) {
        float a = w[j] * winv;
        const float4* Vr = sV + topi[j] * 256;
        #pragma unroll
        for (int i = 0; i < 8; i++) {
            float4 vv = Vr[lane + 32 * i];
            r[i].x += a * vv.x; r[i].y += a * vv.y;
            r[i].z += a * vv.z; r[i].w += a * vv.w;
        }
    }
    float ssum = 0.f;
    #pragma unroll
    for (int i = 0; i < 8; i++)
        ssum += r[i].x*r[i].x + r[i].y*r[i].y + r[i].z*r[i].z + r[i].w*r[i].w;
    ssum = wred(ssum);
    float rinv = frsqrt(ssum * (1.f / DIMC) + EPSv);

    const float2* g2 = (const float2*)gain;
    float4* orow = (float4*)(out + (size_t)token * NC);
    #pragma unroll
    for (int i = 0; i < 8; i++) {
        float2 g = g2[lane + 32 * i];
        float4 o;
        o.x = r[i].x * rinv * g.x; o.y = r[i].y * rinv * g.x;
        o.z = r[i].z * rinv * g.y; o.w = r[i].w * rinv * g.y;
        orow[lane + 32 * i] = o;
    }
}

/* ------------------------------------------------------------------ */
extern "C" void kernel_launch(void* const* d_in, const int* in_sizes, int n_in,
                              void* d_out, int out_size) {
    const float* z    = (const float*)d_in[0];
    const float* sk   = (const float*)d_in[1];
    const float* sv   = (const float*)d_in[2];
    const float* sm   = (const float*)d_in[3];
    const float* Wsr  = (const float*)d_in[4];
    const float* Wsi  = (const float*)d_in[5];
    const float* sb   = (const float*)d_in[6];
    const float* ns   = (const float*)d_in[7];
    const float* Wekr = (const float*)d_in[8];
    const float* Weki = (const float*)d_in[9];
    const float* Wevr = (const float*)d_in[10];
    const float* Wevi = (const float*)d_in[11];
    const float* Wrqr = (const float*)d_in[12];
    const float* Wrqi = (const float*)d_in[13];
    const float* gain = (const float*)d_in[14];
    float* out = (float*)d_out;

    static bool init_done = false;
    static cudaStream_t s1;
    static cudaEvent_t evRoot, evStats, evQ;
    if (!init_done) {
        cudaFuncSetAttribute(k_attn, cudaFuncAttributeMaxDynamicSharedMemorySize, 131072);
        cudaFuncSetAttribute(k_qgemm_mma, cudaFuncAttributeMaxDynamicSharedMemorySize, QSMEM);
        cudaFuncSetAttribute(k_dotgemm, cudaFuncAttributeMaxDynamicSharedMemorySize, DSMEM);
        cudaStreamCreateWithFlags(&s1, cudaStreamNonBlocking);
        cudaEventCreateWithFlags(&evRoot, cudaEventDisableTiming);
        cudaEventCreateWithFlags(&evStats, cudaEventDisableTiming);
        cudaEventCreateWithFlags(&evQ, cudaEventDisableTiming);
        init_done = true;
    }

    /* fork: s1 runs build_bt + qgemm concurrently with the event chain */
    cudaEventRecord(evRoot, 0);
    cudaStreamWaitEvent(s1, evRoot, 0);
    k_build_bt<<<dim3(16, 16), 256, 0, s1>>>(Wrqr, Wrqi);

    k_stats<<<4096, 256>>>(z, Wsr, Wsi);
    cudaEventRecord(evStats, 0);
    cudaStreamWaitEvent(s1, evStats, 0);
    k_qgemm_mma<<<dim3(NC / BN, NT / BM), 512, QSMEM, s1>>>();
    cudaEventRecord(evQ, s1);

    k_runs<<<Bb, 256>>>(out, sb, ns);
    k_evec<<<Bb * SS, 256>>>(z, out);
    k_eventkv<<<dim3(Bb, SS / 2), 512>>>(Wekr, Weki, Wevr, Wevi, sk, sv, sm, out);
    k_udot<<<dim3(Bb, SS / 8, 2), 256>>>(out);
    k_dotgemm<<<NT / DM, 256, DSMEM>>>();

    /* join: attn needs qp from s1 */
    cudaStreamWaitEvent(0, evQ, 0);
    k_attn<<<NT / 32, 1024, 131072>>>(out, gain);
}